// round 15
// baseline (speedup 1.0000x reference)
#include <cuda_runtime.h>
#include <cuda_fp16.h>
#include <math.h>
#include <stdint.h>

#define BB    128
#define TT    256
#define INDIM 300
#define HH    512
#define NCLS  45
#define LNEPS 1e-5f

#define GRID_P  148
#define NSTEPS  258

// persist smem layout (byte offsets)
#define SM_BH   0
#define SM_BL   32768
#define SM_A    65536
#define SM_SBH  98304
#define SM_SBL  102400
#define SM_A2   106496
#define SM_LNC  139264
#define DSMEM   145408

// x0mma smem layout
#define X0_AH  0
#define X0_AL  16384
#define X0_BH  32768
#define X0_BL  49152
#define X0_DS  65536

// ---------- device scratch ----------
__device__ float g_W0[2 * INDIM * HH];
__device__ float g_b0[2 * HH];
__device__ __align__(16) __half g_W0h[2 * HH * 320];        // [d][n][k320]
__device__ __align__(16) __half g_W0l[2 * HH * 320];
__device__ __align__(16) __half g_Xh[2 * 32768 * 320];      // [d][m][k320]
__device__ __align__(16) __half g_Xl[2 * 32768 * 320];
__device__ float g_X0[2 * TT * BB * HH];
__device__ __align__(16) __half g_Bh[10 * HH * HH];         // [mat][n][k512] hi
__device__ __align__(16) __half g_Bl[10 * HH * HH];         // lo
__device__ __align__(16) __half g_hh[2 * 3 * BB * HH];      // h fp16
__device__ float g_pp[2 * 3 * 8 * BB * HH];                 // slots (d*3+l)*8+kc
__device__ float g_o2[2 * TT * BB * HH];
__device__ float g_cb[6 * HH];
__device__ unsigned g_barc;                                  // barrier A counter (148 arrivals)
__device__ unsigned g_barc2;                                 // barrier B counter (96 arrivals)
__device__ __align__(128) unsigned g_senseA[8 * 32];         // 8 replicated copies, 128B apart
__device__ __align__(128) unsigned g_senseB[8 * 32];

// ---------- helpers ----------
__device__ __forceinline__ uint32_t smem_u32(const void* p) {
    uint32_t a;
    asm("{ .reg .u64 t; cvta.to.shared.u64 t, %1; cvt.u32.u64 %0, t; }" : "=r"(a) : "l"(p));
    return a;
}

// Barrier A: all 148 arrive (publishes pp); only LN CTAs (doPoll) wait.
// Sense word replicated 8x across distinct 128B lines to kill poll contention.
__device__ __forceinline__ void gsync_all(unsigned target, bool doPoll, int scopy) {
    __syncthreads();
    if (threadIdx.x == 0) {
        unsigned old;
        asm volatile("atom.add.acq_rel.gpu.u32 %0, [%1], 1;" : "=r"(old) : "l"(&g_barc) : "memory");
        if (old == (unsigned)(GRID_P - 1)) {
            asm volatile("st.relaxed.gpu.u32 [%0], 0;" :: "l"(&g_barc) : "memory");
#pragma unroll
            for (int i = 0; i < 8; i++)
                asm volatile("st.release.gpu.u32 [%0], %1;"
                             :: "l"(&g_senseA[i * 32]), "r"(target) : "memory");
        } else if (doPoll) {
            unsigned sv;
            do {
                asm volatile("ld.acquire.gpu.u32 %0, [%1];"
                             : "=r"(sv) : "l"(&g_senseA[scopy * 32]) : "memory");
            } while (sv < target);
        }
    }
    __syncthreads();
}

// Barrier B: only 96 LN CTAs arrive (publishes h); everyone waits.
__device__ __forceinline__ void gsync_ln(unsigned target, bool arrive, int scopy) {
    __syncthreads();
    if (threadIdx.x == 0) {
        if (arrive) {
            unsigned old;
            asm volatile("atom.add.acq_rel.gpu.u32 %0, [%1], 1;" : "=r"(old) : "l"(&g_barc2) : "memory");
            if (old == 95u) {
                asm volatile("st.relaxed.gpu.u32 [%0], 0;" :: "l"(&g_barc2) : "memory");
#pragma unroll
                for (int i = 0; i < 8; i++)
                    asm volatile("st.release.gpu.u32 [%0], %1;"
                                 :: "l"(&g_senseB[i * 32]), "r"(target) : "memory");
            }
        }
        unsigned sv;
        do {
            asm volatile("ld.acquire.gpu.u32 %0, [%1];"
                         : "=r"(sv) : "l"(&g_senseB[scopy * 32]) : "memory");
        } while (sv < target);
    }
    __syncthreads();
}

// ---------- fused prologue A: w0 GEMM + init + xconv + convw ----------
// grid: [0,48) w0 | [48,1584) init | [1584,5680) xconv | [5680,8240) convw
__global__ void __launch_bounds__(256)
prolog_a(const float* __restrict__ x, const float* __restrict__ rx,
         const float* __restrict__ W_emb, const float* __restrict__ b_emb,
         const float* __restrict__ Wx_l2r, const float* __restrict__ bx_l2r,
         const float* __restrict__ Wx_r2l, const float* __restrict__ bx_r2l,
         const float* __restrict__ Wh_l2r, const float* __restrict__ bh_l2r,
         const float* __restrict__ Wh_r2l, const float* __restrict__ bh_r2l) {
    __shared__ float shf[16 * 136 + 16 * 64];
    const int blk = blockIdx.x;
    const int tid = threadIdx.x;

    if (blk < 48) {
        const int d = blk / 24;
        const int m0 = ((blk % 24) / 8) * 128;
        const int n0 = (blk % 8) * 64;
        const float* Wx0 = d ? Wx_r2l : Wx_l2r;
        const float* bx0 = d ? bx_r2l : bx_l2r;
        float (*As)[136] = (float(*)[136])shf;
        float (*Bs)[64]  = (float(*)[64])(shf + 16 * 136);
        const int ty = tid >> 4, tx = tid & 15;
        float acc[8][4];
#pragma unroll
        for (int i = 0; i < 8; i++)
#pragma unroll
            for (int j = 0; j < 4; j++) acc[i][j] = 0.f;

        for (int k0 = 0; k0 < HH; k0 += 16) {
            {
                const int row = tid >> 2, c4 = (tid & 3) * 4;
#pragma unroll
                for (int rr = 0; rr < 2; rr++) {
                    int r = row + rr * 64;
                    int gm = m0 + r;
                    float4 av = make_float4(0.f, 0.f, 0.f, 0.f);
                    if (gm < INDIM)       av = *(const float4*)(W_emb + (size_t)gm * HH + k0 + c4);
                    else if (gm == INDIM) av = *(const float4*)(b_emb + k0 + c4);
                    As[c4 + 0][r] = av.x; As[c4 + 1][r] = av.y;
                    As[c4 + 2][r] = av.z; As[c4 + 3][r] = av.w;
                }
            }
            {
                const int row = tid >> 4, c4 = (tid & 15) * 4;
                float4 bv = *(const float4*)(Wx0 + (size_t)(k0 + row) * HH + n0 + c4);
                *(float4*)(&Bs[row][c4]) = bv;
            }
            __syncthreads();
#pragma unroll
            for (int kk = 0; kk < 16; kk++) {
                float4 a0 = *(const float4*)(&As[kk][ty * 8]);
                float4 a1 = *(const float4*)(&As[kk][ty * 8 + 4]);
                float4 b4 = *(const float4*)(&Bs[kk][tx * 4]);
                float a[8] = {a0.x, a0.y, a0.z, a0.w, a1.x, a1.y, a1.z, a1.w};
                float b[4] = {b4.x, b4.y, b4.z, b4.w};
#pragma unroll
                for (int i = 0; i < 8; i++)
#pragma unroll
                    for (int j = 0; j < 4; j++) acc[i][j] = fmaf(a[i], b[j], acc[i][j]);
            }
            __syncthreads();
        }
#pragma unroll
        for (int i = 0; i < 8; i++) {
            int gm = m0 + ty * 8 + i;
            int gn = n0 + tx * 4;
            if (gm < INDIM) {
#pragma unroll
                for (int j = 0; j < 4; j++) g_W0[(size_t)(d * INDIM + gm) * HH + gn + j] = acc[i][j];
            } else if (gm == INDIM) {
#pragma unroll
                for (int j = 0; j < 4; j++) g_b0[d * HH + gn + j] = acc[i][j] + bx0[gn + j];
            }
        }
    } else if (blk < 1584) {
        int i = (blk - 48) * 256 + tid;
        if (i == 0) { g_barc = 0; g_barc2 = 0; }
        if (i < 8 * 32 * 2) {
            if (i < 8 * 32) g_senseA[i] = 0;
            else            g_senseB[i - 8 * 32] = 0;
        }
        if (i < 2 * 3 * BB * HH) g_hh[i] = __float2half(0.f);
        if (i < 6 * HH) {
            int task = i / HH, j = i % HH;
            int dd = task / 3, ll = task - dd * 3;
            const float* bx = dd ? bx_r2l : bx_l2r;
            const float* bh = dd ? bh_r2l : bh_l2r;
            float cb = bh[ll * HH + j];
            if (ll != 0) cb += bx[ll * HH + j];
            g_cb[i] = cb;
        }
    } else if (blk < 5680) {
        const int bx = blk - 1584;
        const int row = bx * 16 + (tid >> 4);
        const int d = row >> 15;
        const int m = row & 32767;
        const float* src = d ? rx : x;
        const float2* s2 = (const float2*)(src + (size_t)m * INDIM);
        __half2* dh = (__half2*)g_Xh + (size_t)row * 160;
        __half2* dl = (__half2*)g_Xl + (size_t)row * 160;
#pragma unroll
        for (int k = 0; k < 10; k++) {
            int c2 = (tid & 15) + 16 * k;
            float2 v = (c2 < 150) ? s2[c2] : make_float2(0.f, 0.f);
            __half hx = __float2half(v.x), hy = __float2half(v.y);
            __half lx = __float2half(v.x - __half2float(hx));
            __half ly = __float2half(v.y - __half2float(hy));
            dh[c2] = __halves2half2(hx, hy);
            dl[c2] = __halves2half2(lx, ly);
        }
    } else {
        const int c = blk - 5680;
        const int mat = c / 256;
        const int rem = c % 256;
        const int k0 = (rem / 16) * 32, n0 = (rem % 16) * 32;
        const int d = mat / 5, mm = mat % 5;
        const float* Wx = d ? Wx_r2l : Wx_l2r;
        const float* Wh = d ? Wh_r2l : Wh_l2r;
        const float* W;
        if      (mm == 0) W = Wh;
        else if (mm == 1) W = Wx + (size_t)1 * HH * HH;
        else if (mm == 2) W = Wh + (size_t)1 * HH * HH;
        else if (mm == 3) W = Wx + (size_t)2 * HH * HH;
        else              W = Wh + (size_t)2 * HH * HH;
        float (*tile)[33] = (float(*)[33])shf;
        const int tx = tid & 31, ty = tid >> 5;
        for (int r = ty; r < 32; r += 8)
            tile[r][tx] = W[(size_t)(k0 + r) * HH + n0 + tx];
        __syncthreads();
        for (int r = ty; r < 32; r += 8) {
            float v = tile[tx][r];
            __half hi = __float2half(v);
            __half lo = __float2half(v - __half2float(hi));
            size_t dst = ((size_t)mat * HH + n0 + r) * HH + k0 + tx;
            g_Bh[dst] = hi;
            g_Bl[dst] = lo;
        }
    }
}

// ---------- W0 fp32 [d][k300][n] -> fp16 hi/lo transposed [d][n][k320] ----------
__global__ void w0conv_kernel() {
    __shared__ float tile[32][33];
    const int d = blockIdx.z;
    const int k0 = blockIdx.y * 32, n0 = blockIdx.x * 32;
    const int tx = threadIdx.x;
    for (int r = threadIdx.y; r < 32; r += 8) {
        int k = k0 + r;
        tile[r][tx] = (k < INDIM) ? g_W0[(size_t)(d * INDIM + k) * HH + n0 + tx] : 0.f;
    }
    __syncthreads();
    for (int r = threadIdx.y; r < 32; r += 8) {
        float v = tile[tx][r];
        __half hi = __float2half(v);
        __half lo = __float2half(v - __half2float(hi));
        size_t dst = ((size_t)d * HH + n0 + r) * 320 + k0 + tx;
        g_W0h[dst] = hi;
        g_W0l[dst] = lo;
    }
}

// ---------- smem tile loaders (16B-chunk XOR swizzle); L2-only loads ----------
__device__ __forceinline__ void load_t128(uint32_t dst, const __half* __restrict__ src) {
    const int tid = threadIdx.x;
#pragma unroll
    for (int it = 0; it < 8; it++) {
        int idx = it * 256 + tid;
        int r = idx >> 4, c = idx & 15;
        uint4 v = __ldcg((const uint4*)(src + (size_t)r * 512 + c * 8));
        uint32_t a = dst + r * 256 + (((uint32_t)(c ^ (r & 7))) << 4);
        asm volatile("st.shared.v4.b32 [%0], {%1,%2,%3,%4};"
                     :: "r"(a), "r"(v.x), "r"(v.y), "r"(v.z), "r"(v.w) : "memory");
    }
}
// 16 rows x 128 halfs
__device__ __forceinline__ void load_t16(uint32_t dst, const __half* __restrict__ src) {
    const int tid = threadIdx.x;
    int r = tid >> 4, c = tid & 15;
    uint4 v = __ldcg((const uint4*)(src + (size_t)r * 512 + c * 8));
    uint32_t a = dst + r * 256 + (((uint32_t)(c ^ (r & 7))) << 4);
    asm volatile("st.shared.v4.b32 [%0], {%1,%2,%3,%4};"
                 :: "r"(a), "r"(v.x), "r"(v.y), "r"(v.z), "r"(v.w) : "memory");
}
// 128 rows x 64 halfs, src row stride 320 halfs
__device__ __forceinline__ void load_t64(uint32_t dst, const __half* __restrict__ src) {
    const int tid = threadIdx.x;
#pragma unroll
    for (int it = 0; it < 4; it++) {
        int idx = it * 256 + tid;
        int r = idx >> 3, c = idx & 7;
        uint4 v = *(const uint4*)(src + (size_t)r * 320 + c * 8);
        uint32_t a = dst + r * 128 + (((uint32_t)(c ^ (r & 7))) << 4);
        asm volatile("st.shared.v4.b32 [%0], {%1,%2,%3,%4};"
                     :: "r"(a), "r"(v.x), "r"(v.y), "r"(v.z), "r"(v.w) : "memory");
    }
}

#define MMA_F16(acc, a0, a1, a2, a3, b0, b1) \
    asm volatile( \
        "mma.sync.aligned.m16n8k16.row.col.f32.f16.f16.f32 " \
        "{%0,%1,%2,%3}, {%4,%5,%6,%7}, {%8,%9}, {%0,%1,%2,%3};" \
        : "+f"((acc)[0]), "+f"((acc)[1]), "+f"((acc)[2]), "+f"((acc)[3]) \
        : "r"(a0), "r"(a1), "r"(a2), "r"(a3), "r"(b0), "r"(b1))

#define LDSM4(r0, r1, r2, r3, addr) \
    asm volatile("ldmatrix.sync.aligned.m8n8.x4.shared.b16 {%0,%1,%2,%3}, [%4];" \
                 : "=r"(r0), "=r"(r1), "=r"(r2), "=r"(r3) : "r"(addr))

// ---------- main fused GEMM: acc = A(128x128) @ (Bh+Bl)(128n x 128k)^T ----------
__device__ __forceinline__ void gemm_main(uint32_t smA, uint32_t smBh, uint32_t smBl,
                                          const int aoff[2], const int aswz[2], int ahi,
                                          const int boff[4], const int bswz[4], int bhi,
                                          float acc[2][8][4]) {
#pragma unroll
    for (int mt = 0; mt < 2; mt++)
#pragma unroll
        for (int nt = 0; nt < 8; nt++)
#pragma unroll
            for (int i = 0; i < 4; i++) acc[mt][nt][i] = 0.f;
#pragma unroll 2
    for (int ks = 0; ks < 8; ks++) {
        uint32_t a[2][4];
#pragma unroll
        for (int mt = 0; mt < 2; mt++) {
            uint32_t addr = smA + aoff[mt] + ((uint32_t)((ks * 2 + ahi) ^ aswz[mt]) << 4);
            LDSM4(a[mt][0], a[mt][1], a[mt][2], a[mt][3], addr);
        }
#pragma unroll
        for (int half = 0; half < 2; half++) {
            uint32_t smB = half ? smBl : smBh;
            uint32_t bq[4][4];
#pragma unroll
            for (int np = 0; np < 4; np++) {
                uint32_t addr = smB + boff[np] + ((uint32_t)((ks * 2 + bhi) ^ bswz[np]) << 4);
                LDSM4(bq[np][0], bq[np][1], bq[np][2], bq[np][3], addr);
            }
#pragma unroll
            for (int mt = 0; mt < 2; mt++)
#pragma unroll
                for (int nt = 0; nt < 8; nt++) {
                    uint32_t b0 = bq[nt >> 1][(nt & 1) ? 2 : 0];
                    uint32_t b1 = bq[nt >> 1][(nt & 1) ? 3 : 1];
                    MMA_F16(acc[mt][nt], a[mt][0], a[mt][1], a[mt][2], a[mt][3], b0, b1);
                }
        }
    }
}

// ---------- persistent wavefront kernel ----------
__global__ void __launch_bounds__(256, 1)
persist_kernel(const float* __restrict__ ln_g, const float* __restrict__ ln_b) {
    extern __shared__ char smem_raw[];
    const uint32_t sbase = smem_u32(smem_raw);
    const int tid = threadIdx.x;
    const int wid = tid >> 5, lane = tid & 31;
    const int wm = wid & 3, wn = wid >> 2;

    int aoff[2], aswz[2];
#pragma unroll
    for (int mt = 0; mt < 2; mt++) {
        int r = wm * 32 + mt * 16 + (lane & 15);
        aoff[mt] = r * 256;
        aswz[mt] = r & 7;
    }
    const int ahi = lane >> 4;
    int boff[4], bswz[4];
#pragma unroll
    for (int np = 0; np < 4; np++) {
        int nl = wn * 64 + np * 16 + (lane & 7) + ((lane >> 4) << 3);
        boff[np] = nl * 256;
        bswz[np] = nl & 7;
    }
    const int bhi = (lane >> 3) & 1;

    auto decode = [](int u, int& d, int& l, int& ntile, int& kc, int& mat, int& asrc) {
        d = u / 80;
        int r = u % 80;
        if (r < 16)      { l = 0; ntile = r >> 2;        kc = r & 3;
                           mat = d * 5 + 0; asrc = 0; }
        else if (r < 48) { l = 1; int rr = r - 16; ntile = rr >> 3; kc = rr & 7;
                           if (kc < 4) { mat = d * 5 + 1; asrc = 0; }
                           else        { mat = d * 5 + 2; asrc = 1; } }
        else             { l = 2; int rr = r - 48; ntile = rr >> 3; kc = rr & 7;
                           if (kc < 4) { mat = d * 5 + 3; asrc = 1; }
                           else        { mat = d * 5 + 4; asrc = 2; } }
    };

    const int cta = blockIdx.x;
    const bool isLN = (cta < 96);
    const int scopy = cta & 7;

    int dM, lM, ntM, kcM, matM, asM;
    decode(cta, dM, lM, ntM, kcM, matM, asM);
    const int koffM = (kcM & 3) * 128;
    const int n0M = ntM * 128;
    const __half* Amain = g_hh + (size_t)(dM * 3 + asM) * BB * HH + koffM;
    float* dstM = g_pp + (size_t)((dM * 3 + lM) * 8 + kcM) * (BB * HH) + n0M;
    load_t128(sbase + SM_BH, g_Bh + ((size_t)matM * HH + n0M) * HH + koffM);
    load_t128(sbase + SM_BL, g_Bl + ((size_t)matM * HH + n0M) * HH + koffM);

    // sub slices: units 148..159 split into 96 N=16 slices on CTAs 48..143
    const bool hasSub = (cta >= 48 && cta < 144);
    int lS = 0;
    const __half* Asub = nullptr;
    float* dstS = nullptr;
    if (hasSub) {
        int j = cta - 48;
        int su = 148 + (j >> 3);
        int nsub = j & 7;
        int dS, ntS, kcS, matS, asS;
        decode(su, dS, lS, ntS, kcS, matS, asS);
        int koffS = (kcS & 3) * 128;
        int n0S = ntS * 128 + nsub * 16;
        Asub = g_hh + (size_t)(dS * 3 + asS) * BB * HH + koffS;
        dstS = g_pp + (size_t)((dS * 3 + lS) * 8 + kcS) * (BB * HH) + n0S;
        load_t16(sbase + SM_SBH, g_Bh + ((size_t)matS * HH + n0S) * HH + koffS);
        load_t16(sbase + SM_SBL, g_Bl + ((size_t)matS * HH + n0S) * HH + koffS);
    }

    // LN constants in smem (one task per LN CTA)
    float* lncb = (float*)(smem_raw + SM_LNC);
    float* lng  = lncb + HH;
    float* lnb  = lncb + 2 * HH;
    const int taskL = cta >> 4;                 // valid for cta < 96
    const int ddL = (taskL >= 3) ? 1 : 0;
    const int llL = taskL - ddL * 3;
    if (isLN) {
        for (int i = tid; i < HH; i += 256) {
            lncb[i] = g_cb[taskL * HH + i];
            lng[i]  = ln_g[llL * HH + i];
            lnb[i]  = ln_b[llL * HH + i];
        }
    }
    __syncthreads();

    const int er = lane >> 2, ec = (lane & 3) * 2;
    const int ar2 = (wid << 4) + (lane & 15);
    const int aoff2 = ar2 * 256, aswz2 = ar2 & 7;
    const int nl2 = (lane & 7) + ((lane >> 4) << 3);
    const int boff2 = nl2 * 256, bswz2 = nl2 & 7;

    float acc[2][8][4];
    unsigned bt = 0;

    for (int s = 0; s < NSTEPS; s++) {
        const int tM = s - lM;
        const bool runM = (tM >= 0 && tM < TT);
        const int tS = s - lS;
        const bool runS = hasSub && (tS >= 0 && tS < TT);

        if (runM) load_t128(sbase + SM_A, Amain);
        if (runS) load_t128(sbase + SM_A2, Asub);
        __syncthreads();

        if (runM) {
            gemm_main(sbase + SM_A, sbase + SM_BH, sbase + SM_BL,
                      aoff, aswz, ahi, boff, bswz, bhi, acc);
#pragma unroll
            for (int mt = 0; mt < 2; mt++) {
                int row0 = wm * 32 + mt * 16 + er;
#pragma unroll
                for (int nt = 0; nt < 8; nt++) {
                    int col = wn * 64 + nt * 8 + ec;
                    __stcg((float2*)(dstM + (size_t)row0 * HH + col),
                           make_float2(acc[mt][nt][0], acc[mt][nt][1]));
                    __stcg((float2*)(dstM + (size_t)(row0 + 8) * HH + col),
                           make_float2(acc[mt][nt][2], acc[mt][nt][3]));
                }
            }
        }
        if (runS) {
            float accs[2][4];
#pragma unroll
            for (int nt = 0; nt < 2; nt++)
#pragma unroll
                for (int i = 0; i < 4; i++) accs[nt][i] = 0.f;
#pragma unroll 2
            for (int ks = 0; ks < 8; ks++) {
                uint32_t a2[4];
                uint32_t addr = sbase + SM_A2 + aoff2 + ((uint32_t)((ks * 2 + ahi) ^ aswz2) << 4);
                LDSM4(a2[0], a2[1], a2[2], a2[3], addr);
#pragma unroll
                for (int half = 0; half < 2; half++) {
                    uint32_t smB = sbase + (half ? SM_SBL : SM_SBH);
                    uint32_t bq[4];
                    uint32_t ba = smB + boff2 + ((uint32_t)((ks * 2 + bhi) ^ bswz2) << 4);
                    LDSM4(bq[0], bq[1], bq[2], bq[3], ba);
                    MMA_F16(accs[0], a2[0], a2[1], a2[2], a2[3], bq[0], bq[1]);
                    MMA_F16(accs[1], a2[0], a2[1], a2[2], a2[3], bq[2], bq[3]);
                }
            }
            int row0 = (wid << 4) + er;
#pragma unroll
            for (int nt = 0; nt < 2; nt++) {
                int col = nt * 8 + ec;
                __stcg((float2*)(dstS + (size_t)row0 * HH + col),
                       make_float2(accs[nt][0], accs[nt][1]));
                __stcg((float2*)(dstS + (size_t)(row0 + 8) * HH + col),
                       make_float2(accs[nt][2], accs[nt][3]));
            }
        }

        gsync_all(++bt, isLN, scopy);

        // ---- LN + tanh: warp-per-row, one task per CTA (cta<96) ----
        if (isLN) {
            const int b = ((cta << 3) + wid) & 127;
            const int tt2 = s - llL;
            if (tt2 >= 0 && tt2 < TT) {
                const int j0 = lane << 4;
                const float* ppb = g_pp + (size_t)taskL * 8 * (BB * HH) + (size_t)b * HH + j0;
                float4 v0 = ((const float4*)(lncb + j0))[0];
                float4 v1 = ((const float4*)(lncb + j0))[1];
                float4 v2 = ((const float4*)(lncb + j0))[2];
                float4 v3 = ((const float4*)(lncb + j0))[3];
                if (llL == 0) {
                    const float* x0p = g_X0 + ((size_t)(ddL * TT + tt2) * BB + b) * HH + j0;
                    {
                        float4 q0 = __ldg((const float4*)x0p);
                        float4 q1 = __ldg((const float4*)x0p + 1);
                        float4 q2 = __ldg((const float4*)x0p + 2);
                        float4 q3 = __ldg((const float4*)x0p + 3);
                        v0.x += q0.x; v0.y += q0.y; v0.z += q0.z; v0.w += q0.w;
                        v1.x += q1.x; v1.y += q1.y; v1.z += q1.z; v1.w += q1.w;
                        v2.x += q2.x; v2.y += q2.y; v2.z += q2.z; v2.w += q2.w;
                        v3.x += q3.x; v3.y += q3.y; v3.z += q3.z; v3.w += q3.w;
                    }
#pragma unroll
                    for (int c = 0; c < 4; c++) {
                        const float4* p4 = (const float4*)(ppb + (size_t)c * (BB * HH));
                        float4 q0 = __ldcg(p4), q1 = __ldcg(p4 + 1);
                        float4 q2 = __ldcg(p4 + 2), q3 = __ldcg(p4 + 3);
                        v0.x += q0.x; v0.y += q0.y; v0.z += q0.z; v0.w += q0.w;
                        v1.x += q1.x; v1.y += q1.y; v1.z += q1.z; v1.w += q1.w;
                        v2.x += q2.x; v2.y += q2.y; v2.z += q2.z; v2.w += q2.w;
                        v3.x += q3.x; v3.y += q3.y; v3.z += q3.z; v3.w += q3.w;
                    }
                } else {
#pragma unroll
                    for (int c = 0; c < 8; c++) {
                        const float4* p4 = (const float4*)(ppb + (size_t)c * (BB * HH));
                        float4 q0 = __ldcg(p4), q1 = __ldcg(p4 + 1);
                        float4 q2 = __ldcg(p4 + 2), q3 = __ldcg(p4 + 3);
                        v0.x += q0.x; v0.y += q0.y; v0.z += q0.z; v0.w += q0.w;
                        v1.x += q1.x; v1.y += q1.y; v1.z += q1.z; v1.w += q1.w;
                        v2.x += q2.x; v2.y += q2.y; v2.z += q2.z; v2.w += q2.w;
                        v3.x += q3.x; v3.y += q3.y; v3.z += q3.z; v3.w += q3.w;
                    }
                }
                float s1 = (v0.x + v0.y + v0.z + v0.w) + (v1.x + v1.y + v1.z + v1.w)
                         + (v2.x + v2.y + v2.z + v2.w) + (v3.x + v3.y + v3.z + v3.w);
                float s2 = (v0.x * v0.x + v0.y * v0.y + v0.z * v0.z + v0.w * v0.w)
                         + (v1.x * v1.x + v1.y * v1.y + v1.z * v1.z + v1.w * v1.w)
                         + (v2.x * v2.x + v2.y * v2.y + v2.z * v2.z + v2.w * v2.w)
                         + (v3.x * v3.x + v3.y * v3.y + v3.z * v3.z + v3.w * v3.w);
#pragma unroll
                for (int o = 16; o > 0; o >>= 1) {
                    s1 += __shfl_xor_sync(0xffffffffu, s1, o);
                    s2 += __shfl_xor_sync(0xffffffffu, s2, o);
                }
                const float mean = s1 * (1.f / HH);
                const float var  = s2 * (1.f / HH) - mean * mean;
                const float inv  = rsqrtf(var + LNEPS);
                const float4* gg = (const float4*)(lng + j0);
                const float4* bb = (const float4*)(lnb + j0);
                float hs[16];
#pragma unroll
                for (int q = 0; q < 4; q++) {
                    float4 vq = (q == 0) ? v0 : (q == 1) ? v1 : (q == 2) ? v2 : v3;
                    float4 g4 = gg[q], b4 = bb[q];
                    hs[q * 4 + 0] = tanhf((vq.x - mean) * inv * g4.x + b4.x);
                    hs[q * 4 + 1] = tanhf((vq.y - mean) * inv * g4.y + b4.y);
                    hs[q * 4 + 2] = tanhf((vq.z - mean) * inv * g4.z + b4.z);
                    hs[q * 4 + 3] = tanhf((vq.w - mean) * inv * g4.w + b4.w);
                }
                size_t hidx = (size_t)taskL * BB * HH + (size_t)b * HH + j0;
                uint4 u0, u1;
                {
                    __half2 p0 = __floats2half2_rn(hs[0], hs[1]);
                    __half2 p1 = __floats2half2_rn(hs[2], hs[3]);
                    __half2 p2 = __floats2half2_rn(hs[4], hs[5]);
                    __half2 p3 = __floats2half2_rn(hs[6], hs[7]);
                    u0.x = *(uint32_t*)&p0; u0.y = *(uint32_t*)&p1;
                    u0.z = *(uint32_t*)&p2; u0.w = *(uint32_t*)&p3;
                    __half2 p4 = __floats2half2_rn(hs[8], hs[9]);
                    __half2 p5 = __floats2half2_rn(hs[10], hs[11]);
                    __half2 p6 = __floats2half2_rn(hs[12], hs[13]);
                    __half2 p7 = __floats2half2_rn(hs[14], hs[15]);
                    u1.x = *(uint32_t*)&p4; u1.y = *(uint32_t*)&p5;
                    u1.z = *(uint32_t*)&p6; u1.w = *(uint32_t*)&p7;
                }
                __stcg((uint4*)(g_hh + hidx), u0);
                __stcg((uint4*)(g_hh + hidx) + 1, u1);
                if (llL == 2) {
                    float* o2p = g_o2 + ((size_t)(ddL * TT + tt2) * BB + b) * HH + j0;
#pragma unroll
                    for (int q = 0; q < 4; q++)
                        __stcg((float4*)o2p + q, make_float4(hs[q * 4 + 0], hs[q * 4 + 1],
                                                             hs[q * 4 + 2], hs[q * 4 + 3]));
                }
            }
        }

        gsync_ln(++bt, isLN, scopy);
    }
}

// ---------- X0 = Xh@(W0h+W0l) + Xl@W0h + b0   (fp16 3-product HMMA) ----------
__global__ void __launch_bounds__(256, 1) x0mma_kernel() {
    extern __shared__ char smem_raw[];
    const uint32_t sbase = smem_u32(smem_raw);
    const int tid = threadIdx.x;
    const int wid = tid >> 5, lane = tid & 31;
    const int wm = wid & 3, wn = wid >> 2;
    const int d = blockIdx.z;
    const int m0 = blockIdx.y * 128;
    const int n0 = blockIdx.x * 128;

    const __half* Ah = g_Xh + ((size_t)d * 32768 + m0) * 320;
    const __half* Al = g_Xl + ((size_t)d * 32768 + m0) * 320;
    const __half* Bh = g_W0h + ((size_t)d * HH + n0) * 320;
    const __half* Bl = g_W0l + ((size_t)d * HH + n0) * 320;

    int aoff[2], aswz[2];
#pragma unroll
    for (int mt = 0; mt < 2; mt++) {
        int r = wm * 32 + mt * 16 + (lane & 15);
        aoff[mt] = r * 128;
        aswz[mt] = r & 7;
    }
    const int ahi = lane >> 4;
    int boff[4], bswz[4];
#pragma unroll
    for (int np = 0; np < 4; np++) {
        int nl = wn * 64 + np * 16 + (lane & 7) + ((lane >> 4) << 3);
        boff[np] = nl * 128;
        bswz[np] = nl & 7;
    }
    const int bhi = (lane >> 3) & 1;

    float acc[2][8][4];
#pragma unroll
    for (int mt = 0; mt < 2; mt++)
#pragma unroll
        for (int nt = 0; nt < 8; nt++)
#pragma unroll
            for (int i = 0; i < 4; i++) acc[mt][nt][i] = 0.f;

    for (int kc = 0; kc < 5; kc++) {
        __syncthreads();
        load_t64(sbase + X0_AH, Ah + kc * 64);
        load_t64(sbase + X0_AL, Al + kc * 64);
        load_t64(sbase + X0_BH, Bh + kc * 64);
        load_t64(sbase + X0_BL, Bl + kc * 64);
        __syncthreads();
#pragma unroll
        for (int ks = 0; ks < 4; ks++) {
            uint32_t ah[2][4], al[2][4];
#pragma unroll
            for (int mt = 0; mt < 2; mt++) {
                uint32_t sw = (uint32_t)((ks * 2 + ahi) ^ aswz[mt]) << 4;
                LDSM4(ah[mt][0], ah[mt][1], ah[mt][2], ah[mt][3], sbase + X0_AH + aoff[mt] + sw);
                LDSM4(al[mt][0], al[mt][1], al[mt][2], al[mt][3], sbase + X0_AL + aoff[mt] + sw);
            }
            uint32_t bh[4][4], bl[4][4];
#pragma unroll
            for (int np = 0; np < 4; np++) {
                uint32_t sw = (uint32_t)((ks * 2 + bhi) ^ bswz[np]) << 4;
                LDSM4(bh[np][0], bh[np][1], bh[np][2], bh[np][3], sbase + X0_BH + boff[np] + sw);
                LDSM4(bl[np][0], bl[np][1], bl[np][2], bl[np][3], sbase + X0_BL + boff[np] + sw);
            }
#pragma unroll
            for (int mt = 0; mt < 2; mt++)
#pragma unroll
                for (int nt = 0; nt < 8; nt++) {
                    int q = nt >> 1;
                    int i0 = (nt & 1) ? 2 : 0, i1 = (nt & 1) ? 3 : 1;
                    MMA_F16(acc[mt][nt], ah[mt][0], ah[mt][1], ah[mt][2], ah[mt][3],
                            bh[q][i0], bh[q][i1]);
                    MMA_F16(acc[mt][nt], ah[mt][0], ah[mt][1], ah[mt][2], ah[mt][3],
                            bl[q][i0], bl[q][i1]);
                    MMA_F16(acc[mt][nt], al[mt][0], al[mt][1], al[mt][2], al[mt][3],
                            bh[q][i0], bh[q][i1]);
                }
        }
    }

    const int er = lane >> 2, ec = (lane & 3) * 2;
    const int b = m0 >> 8;
    const int tb = m0 & 255;
#pragma unroll
    for (int mt = 0; mt < 2; mt++) {
#pragma unroll
        for (int nt = 0; nt < 8; nt++) {
            int col = n0 + wn * 64 + nt * 8 + ec;
            float b0a = g_b0[d * HH + col];
            float b0b = g_b0[d * HH + col + 1];
#pragma unroll
            for (int rr = 0; rr < 2; rr++) {
                int rowin = wm * 32 + mt * 16 + er + rr * 8;
                int t = tb + rowin;
                float* dst = g_X0 + ((size_t)(d * TT + t) * BB + b) * HH + col;
                *(float2*)dst = make_float2(acc[mt][nt][rr * 2 + 0] + b0a,
                                            acc[mt][nt][rr * 2 + 1] + b0b);
            }
        }
    }
}

// ---------- gather + concat + FC ----------
__global__ void final_kernel(const int* __restrict__ pad,
                             const float* __restrict__ W_fc, const float* __restrict__ b_fc,
                             float* __restrict__ out) {
    __shared__ float cs[8][1024];
    const int sub  = threadIdx.x >> 6;
    const int lane = threadIdx.x & 63;
    const int r = blockIdx.x * 8 + sub;
    const int b = r >> 8;
    const int t = r & 255;
    const int p = pad[b];
    const int tt = (t < p) ? (p - t - 1) : t;
    const float* a0 = g_o2 + ((size_t)(0 * TT + t)  * BB + b) * HH;
    const float* a1 = g_o2 + ((size_t)(1 * TT + tt) * BB + b) * HH;
#pragma unroll
    for (int i = 0; i < 4; i++) {
        int j = lane * 4 + i * 256;
        float4 vv = (j < 512) ? *(const float4*)(a0 + j) : *(const float4*)(a1 + j - 512);
        *(float4*)(&cs[sub][j]) = vv;
    }
    __syncthreads();
    if (lane < NCLS) {
        float acc = b_fc[lane];
#pragma unroll 8
        for (int k = 0; k < 1024; k++) acc = fmaf(cs[sub][k], W_fc[k * NCLS + lane], acc);
        out[(size_t)r * NCLS + lane] = acc;
    }
}

// ---------- host launcher ----------
extern "C" void kernel_launch(void* const* d_in, const int* in_sizes, int n_in,
                              void* d_out, int out_size) {
    (void)in_sizes; (void)n_in; (void)out_size;
    const float* x      = (const float*)d_in[0];
    const float* rx     = (const float*)d_in[1];
    const int*   pad    = (const int*)  d_in[2];
    const float* W_emb  = (const float*)d_in[4];
    const float* b_emb  = (const float*)d_in[5];
    const float* Wx_l2r = (const float*)d_in[6];
    const float* bx_l2r = (const float*)d_in[7];
    const float* Wh_l2r = (const float*)d_in[8];
    const float* bh_l2r = (const float*)d_in[9];
    const float* Wx_r2l = (const float*)d_in[10];
    const float* bx_r2l = (const float*)d_in[11];
    const float* Wh_r2l = (const float*)d_in[12];
    const float* bh_r2l = (const float*)d_in[13];
    const float* ln_g   = (const float*)d_in[14];
    const float* ln_b   = (const float*)d_in[15];
    const float* W_fc   = (const float*)d_in[16];
    const float* b_fc   = (const float*)d_in[17];
    float* out = (float*)d_out;

    static int attr_done = 0;
    if (!attr_done) {
        cudaFuncSetAttribute(persist_kernel, cudaFuncAttributeMaxDynamicSharedMemorySize, DSMEM);
        cudaFuncSetAttribute(x0mma_kernel, cudaFuncAttributeMaxDynamicSharedMemorySize, X0_DS);
        attr_done = 1;
    }

    // launch order chosen so persist_kernel is the 4th launch (= ncu capture slot)
    prolog_a<<<8240, 256>>>(x, rx, W_emb, b_emb, Wx_l2r, bx_l2r, Wx_r2l, bx_r2l,
                            Wh_l2r, bh_l2r, Wh_r2l, bh_r2l);
    w0conv_kernel<<<dim3(16, 10, 2), dim3(32, 8)>>>();
    x0mma_kernel<<<dim3(4, 256, 2), 256, X0_DS>>>();

    persist_kernel<<<GRID_P, 256, DSMEM>>>(ln_g, ln_b);

    final_kernel<<<4096, 512>>>(pad, W_fc, b_fc, out);
}

// round 16
// speedup vs baseline: 1.3685x; 1.3685x over previous
#include <cuda_runtime.h>
#include <cuda_fp16.h>
#include <math.h>
#include <stdint.h>

#define BB    128
#define TT    256
#define INDIM 300
#define HH    512
#define NCLS  45
#define LNEPS 1e-5f

#define GRID_P  148
#define NSTEPS  258

// persist smem layout (byte offsets)
#define SM_BH   0
#define SM_BL   32768
#define SM_A    65536
#define SM_SBH  98304
#define SM_SBL  102400
#define SM_A2   106496
#define SM_LNC  139264
#define DSMEM   145408

// x0mma smem layout
#define X0_AH  0
#define X0_AL  16384
#define X0_BH  32768
#define X0_BL  49152
#define X0_DS  65536

// ---------- device scratch ----------
__device__ float g_W0[2 * INDIM * HH];
__device__ float g_b0[2 * HH];
__device__ __align__(16) __half g_W0h[2 * HH * 320];        // [d][n][k320]
__device__ __align__(16) __half g_W0l[2 * HH * 320];
__device__ __align__(16) __half g_Xh[2 * 32768 * 320];      // [d][m][k320]
__device__ __align__(16) __half g_Xl[2 * 32768 * 320];
__device__ float g_X0[2 * TT * BB * HH];
__device__ __align__(16) __half g_Bh[10 * HH * HH];         // [mat][n][k512] hi
__device__ __align__(16) __half g_Bl[10 * HH * HH];         // lo
__device__ __align__(16) __half g_hh[2 * 3 * BB * HH];      // h fp16
__device__ float g_pp[2 * 3 * 8 * BB * HH];                 // slots (d*3+l)*8+kc
__device__ float g_o2[2 * TT * BB * HH];
__device__ float g_cb[6 * HH];
__device__ unsigned g_barc;                                  // barrier A counter (148 arrivals)
__device__ unsigned g_sense;                                 // barrier A epoch
__device__ unsigned g_barc2;                                 // barrier B counter (96 arrivals)
__device__ unsigned g_sense2;                                // barrier B epoch

// ---------- helpers ----------
__device__ __forceinline__ uint32_t smem_u32(const void* p) {
    uint32_t a;
    asm("{ .reg .u64 t; cvta.to.shared.u64 t, %1; cvt.u32.u64 %0, t; }" : "=r"(a) : "l"(p));
    return a;
}

// Barrier A: all 148 arrive (publishes pp); only LN CTAs (doPoll) wait.  (R13 winner)
__device__ __forceinline__ void gsync_all(unsigned target, bool doPoll) {
    __syncthreads();
    if (threadIdx.x == 0) {
        unsigned old;
        asm volatile("atom.add.acq_rel.gpu.u32 %0, [%1], 1;" : "=r"(old) : "l"(&g_barc) : "memory");
        if (old == (unsigned)(GRID_P - 1)) {
            asm volatile("st.relaxed.gpu.u32 [%0], 0;" :: "l"(&g_barc) : "memory");
            asm volatile("st.release.gpu.u32 [%0], %1;" :: "l"(&g_sense), "r"(target) : "memory");
        } else if (doPoll) {
            unsigned sv;
            do {
                asm volatile("ld.acquire.gpu.u32 %0, [%1];" : "=r"(sv) : "l"(&g_sense) : "memory");
            } while (sv < target);
        }
    }
    __syncthreads();
}

// Barrier B: only 96 LN CTAs arrive (publishes h); everyone waits.
__device__ __forceinline__ void gsync_ln(unsigned target, bool arrive) {
    __syncthreads();
    if (threadIdx.x == 0) {
        if (arrive) {
            unsigned old;
            asm volatile("atom.add.acq_rel.gpu.u32 %0, [%1], 1;" : "=r"(old) : "l"(&g_barc2) : "memory");
            if (old == 95u) {
                asm volatile("st.relaxed.gpu.u32 [%0], 0;" :: "l"(&g_barc2) : "memory");
                asm volatile("st.release.gpu.u32 [%0], %1;" :: "l"(&g_sense2), "r"(target) : "memory");
            }
        }
        unsigned sv;
        do {
            asm volatile("ld.acquire.gpu.u32 %0, [%1];" : "=r"(sv) : "l"(&g_sense2) : "memory");
        } while (sv < target);
    }
    __syncthreads();
}

// ---------- fused prologue A: w0 GEMM + init + xconv + convw ----------
// grid: [0,48) w0 | [48,1584) init | [1584,5680) xconv | [5680,8240) convw
__global__ void __launch_bounds__(256)
prolog_a(const float* __restrict__ x, const float* __restrict__ rx,
         const float* __restrict__ W_emb, const float* __restrict__ b_emb,
         const float* __restrict__ Wx_l2r, const float* __restrict__ bx_l2r,
         const float* __restrict__ Wx_r2l, const float* __restrict__ bx_r2l,
         const float* __restrict__ Wh_l2r, const float* __restrict__ bh_l2r,
         const float* __restrict__ Wh_r2l, const float* __restrict__ bh_r2l) {
    __shared__ float shf[16 * 136 + 16 * 64];
    const int blk = blockIdx.x;
    const int tid = threadIdx.x;

    if (blk < 48) {
        const int d = blk / 24;
        const int m0 = ((blk % 24) / 8) * 128;
        const int n0 = (blk % 8) * 64;
        const float* Wx0 = d ? Wx_r2l : Wx_l2r;
        const float* bx0 = d ? bx_r2l : bx_l2r;
        float (*As)[136] = (float(*)[136])shf;
        float (*Bs)[64]  = (float(*)[64])(shf + 16 * 136);
        const int ty = tid >> 4, tx = tid & 15;
        float acc[8][4];
#pragma unroll
        for (int i = 0; i < 8; i++)
#pragma unroll
            for (int j = 0; j < 4; j++) acc[i][j] = 0.f;

        for (int k0 = 0; k0 < HH; k0 += 16) {
            {
                const int row = tid >> 2, c4 = (tid & 3) * 4;
#pragma unroll
                for (int rr = 0; rr < 2; rr++) {
                    int r = row + rr * 64;
                    int gm = m0 + r;
                    float4 av = make_float4(0.f, 0.f, 0.f, 0.f);
                    if (gm < INDIM)       av = *(const float4*)(W_emb + (size_t)gm * HH + k0 + c4);
                    else if (gm == INDIM) av = *(const float4*)(b_emb + k0 + c4);
                    As[c4 + 0][r] = av.x; As[c4 + 1][r] = av.y;
                    As[c4 + 2][r] = av.z; As[c4 + 3][r] = av.w;
                }
            }
            {
                const int row = tid >> 4, c4 = (tid & 15) * 4;
                float4 bv = *(const float4*)(Wx0 + (size_t)(k0 + row) * HH + n0 + c4);
                *(float4*)(&Bs[row][c4]) = bv;
            }
            __syncthreads();
#pragma unroll
            for (int kk = 0; kk < 16; kk++) {
                float4 a0 = *(const float4*)(&As[kk][ty * 8]);
                float4 a1 = *(const float4*)(&As[kk][ty * 8 + 4]);
                float4 b4 = *(const float4*)(&Bs[kk][tx * 4]);
                float a[8] = {a0.x, a0.y, a0.z, a0.w, a1.x, a1.y, a1.z, a1.w};
                float b[4] = {b4.x, b4.y, b4.z, b4.w};
#pragma unroll
                for (int i = 0; i < 8; i++)
#pragma unroll
                    for (int j = 0; j < 4; j++) acc[i][j] = fmaf(a[i], b[j], acc[i][j]);
            }
            __syncthreads();
        }
#pragma unroll
        for (int i = 0; i < 8; i++) {
            int gm = m0 + ty * 8 + i;
            int gn = n0 + tx * 4;
            if (gm < INDIM) {
#pragma unroll
                for (int j = 0; j < 4; j++) g_W0[(size_t)(d * INDIM + gm) * HH + gn + j] = acc[i][j];
            } else if (gm == INDIM) {
#pragma unroll
                for (int j = 0; j < 4; j++) g_b0[d * HH + gn + j] = acc[i][j] + bx0[gn + j];
            }
        }
    } else if (blk < 1584) {
        int i = (blk - 48) * 256 + tid;
        if (i == 0) { g_barc = 0; g_sense = 0; g_barc2 = 0; g_sense2 = 0; }
        if (i < 2 * 3 * BB * HH) g_hh[i] = __float2half(0.f);
        if (i < 6 * HH) {
            int task = i / HH, j = i % HH;
            int dd = task / 3, ll = task - dd * 3;
            const float* bx = dd ? bx_r2l : bx_l2r;
            const float* bh = dd ? bh_r2l : bh_l2r;
            float cb = bh[ll * HH + j];
            if (ll != 0) cb += bx[ll * HH + j];
            g_cb[i] = cb;
        }
    } else if (blk < 5680) {
        const int bx = blk - 1584;
        const int row = bx * 16 + (tid >> 4);
        const int d = row >> 15;
        const int m = row & 32767;
        const float* src = d ? rx : x;
        const float2* s2 = (const float2*)(src + (size_t)m * INDIM);
        __half2* dh = (__half2*)g_Xh + (size_t)row * 160;
        __half2* dl = (__half2*)g_Xl + (size_t)row * 160;
#pragma unroll
        for (int k = 0; k < 10; k++) {
            int c2 = (tid & 15) + 16 * k;
            float2 v = (c2 < 150) ? s2[c2] : make_float2(0.f, 0.f);
            __half hx = __float2half(v.x), hy = __float2half(v.y);
            __half lx = __float2half(v.x - __half2float(hx));
            __half ly = __float2half(v.y - __half2float(hy));
            dh[c2] = __halves2half2(hx, hy);
            dl[c2] = __halves2half2(lx, ly);
        }
    } else {
        const int c = blk - 5680;
        const int mat = c / 256;
        const int rem = c % 256;
        const int k0 = (rem / 16) * 32, n0 = (rem % 16) * 32;
        const int d = mat / 5, mm = mat % 5;
        const float* Wx = d ? Wx_r2l : Wx_l2r;
        const float* Wh = d ? Wh_r2l : Wh_l2r;
        const float* W;
        if      (mm == 0) W = Wh;
        else if (mm == 1) W = Wx + (size_t)1 * HH * HH;
        else if (mm == 2) W = Wh + (size_t)1 * HH * HH;
        else if (mm == 3) W = Wx + (size_t)2 * HH * HH;
        else              W = Wh + (size_t)2 * HH * HH;
        float (*tile)[33] = (float(*)[33])shf;
        const int tx = tid & 31, ty = tid >> 5;
        for (int r = ty; r < 32; r += 8)
            tile[r][tx] = W[(size_t)(k0 + r) * HH + n0 + tx];
        __syncthreads();
        for (int r = ty; r < 32; r += 8) {
            float v = tile[tx][r];
            __half hi = __float2half(v);
            __half lo = __float2half(v - __half2float(hi));
            size_t dst = ((size_t)mat * HH + n0 + r) * HH + k0 + tx;
            g_Bh[dst] = hi;
            g_Bl[dst] = lo;
        }
    }
}

// ---------- W0 fp32 [d][k300][n] -> fp16 hi/lo transposed [d][n][k320] ----------
__global__ void w0conv_kernel() {
    __shared__ float tile[32][33];
    const int d = blockIdx.z;
    const int k0 = blockIdx.y * 32, n0 = blockIdx.x * 32;
    const int tx = threadIdx.x;
    for (int r = threadIdx.y; r < 32; r += 8) {
        int k = k0 + r;
        tile[r][tx] = (k < INDIM) ? g_W0[(size_t)(d * INDIM + k) * HH + n0 + tx] : 0.f;
    }
    __syncthreads();
    for (int r = threadIdx.y; r < 32; r += 8) {
        float v = tile[tx][r];
        __half hi = __float2half(v);
        __half lo = __float2half(v - __half2float(hi));
        size_t dst = ((size_t)d * HH + n0 + r) * 320 + k0 + tx;
        g_W0h[dst] = hi;
        g_W0l[dst] = lo;
    }
}

// ---------- smem tile loaders (16B-chunk XOR swizzle); L2-only loads ----------
// 128 rows x 128 halfs, 512 threads
__device__ __forceinline__ void load_t128(uint32_t dst, const __half* __restrict__ src) {
    const int tid = threadIdx.x;
#pragma unroll
    for (int it = 0; it < 4; it++) {
        int idx = it * 512 + tid;
        int r = idx >> 4, c = idx & 15;
        uint4 v = __ldcg((const uint4*)(src + (size_t)r * 512 + c * 8));
        uint32_t a = dst + r * 256 + (((uint32_t)(c ^ (r & 7))) << 4);
        asm volatile("st.shared.v4.b32 [%0], {%1,%2,%3,%4};"
                     :: "r"(a), "r"(v.x), "r"(v.y), "r"(v.z), "r"(v.w) : "memory");
    }
}
// 16 rows x 128 halfs, 512 threads (first 256 act)
__device__ __forceinline__ void load_t16(uint32_t dst, const __half* __restrict__ src) {
    const int tid = threadIdx.x;
    if (tid < 256) {
        int r = tid >> 4, c = tid & 15;
        uint4 v = __ldcg((const uint4*)(src + (size_t)r * 512 + c * 8));
        uint32_t a = dst + r * 256 + (((uint32_t)(c ^ (r & 7))) << 4);
        asm volatile("st.shared.v4.b32 [%0], {%1,%2,%3,%4};"
                     :: "r"(a), "r"(v.x), "r"(v.y), "r"(v.z), "r"(v.w) : "memory");
    }
}
// 128 rows x 64 halfs, src row stride 320 halfs (256 threads, x0mma only)
__device__ __forceinline__ void load_t64(uint32_t dst, const __half* __restrict__ src) {
    const int tid = threadIdx.x;
#pragma unroll
    for (int it = 0; it < 4; it++) {
        int idx = it * 256 + tid;
        int r = idx >> 3, c = idx & 7;
        uint4 v = *(const uint4*)(src + (size_t)r * 320 + c * 8);
        uint32_t a = dst + r * 128 + (((uint32_t)(c ^ (r & 7))) << 4);
        asm volatile("st.shared.v4.b32 [%0], {%1,%2,%3,%4};"
                     :: "r"(a), "r"(v.x), "r"(v.y), "r"(v.z), "r"(v.w) : "memory");
    }
}

#define MMA_F16(acc, a0, a1, a2, a3, b0, b1) \
    asm volatile( \
        "mma.sync.aligned.m16n8k16.row.col.f32.f16.f16.f32 " \
        "{%0,%1,%2,%3}, {%4,%5,%6,%7}, {%8,%9}, {%0,%1,%2,%3};" \
        : "+f"((acc)[0]), "+f"((acc)[1]), "+f"((acc)[2]), "+f"((acc)[3]) \
        : "r"(a0), "r"(a1), "r"(a2), "r"(a3), "r"(b0), "r"(b1))

#define LDSM4(r0, r1, r2, r3, addr) \
    asm volatile("ldmatrix.sync.aligned.m8n8.x4.shared.b16 {%0,%1,%2,%3}, [%4];" \
                 : "=r"(r0), "=r"(r1), "=r"(r2), "=r"(r3) : "r"(addr))

// ---------- persistent wavefront kernel (512 threads, warp tile 32x32) ----------
__global__ void __launch_bounds__(512, 1)
persist_kernel(const float* __restrict__ ln_g, const float* __restrict__ ln_b) {
    extern __shared__ char smem_raw[];
    const uint32_t sbase = smem_u32(smem_raw);
    const int tid = threadIdx.x;
    const int wid = tid >> 5, lane = tid & 31;
    const int wm = wid & 3, wn = wid >> 2;   // 4 x 4 warp grid

    // main-unit lane components: A rows wm*32+mt*16, B cols wn*32+np*16
    int aoff[2], aswz[2];
#pragma unroll
    for (int mt = 0; mt < 2; mt++) {
        int r = wm * 32 + mt * 16 + (lane & 15);
        aoff[mt] = r * 256;
        aswz[mt] = r & 7;
    }
    const int ahi = lane >> 4;
    int boff[2], bswz[2];
#pragma unroll
    for (int np = 0; np < 2; np++) {
        int nl = wn * 32 + np * 16 + (lane & 7) + ((lane >> 4) << 3);
        boff[np] = nl * 256;
        bswz[np] = nl & 7;
    }
    const int bhi = (lane >> 3) & 1;

    auto decode = [](int u, int& d, int& l, int& ntile, int& kc, int& mat, int& asrc) {
        d = u / 80;
        int r = u % 80;
        if (r < 16)      { l = 0; ntile = r >> 2;        kc = r & 3;
                           mat = d * 5 + 0; asrc = 0; }
        else if (r < 48) { l = 1; int rr = r - 16; ntile = rr >> 3; kc = rr & 7;
                           if (kc < 4) { mat = d * 5 + 1; asrc = 0; }
                           else        { mat = d * 5 + 2; asrc = 1; } }
        else             { l = 2; int rr = r - 48; ntile = rr >> 3; kc = rr & 7;
                           if (kc < 4) { mat = d * 5 + 3; asrc = 1; }
                           else        { mat = d * 5 + 4; asrc = 2; } }
    };

    const int cta = blockIdx.x;
    const bool isLN = (cta < 96);

    int dM, lM, ntM, kcM, matM, asM;
    decode(cta, dM, lM, ntM, kcM, matM, asM);
    const int koffM = (kcM & 3) * 128;
    const int n0M = ntM * 128;
    const __half* Amain = g_hh + (size_t)(dM * 3 + asM) * BB * HH + koffM;
    float* dstM = g_pp + (size_t)((dM * 3 + lM) * 8 + kcM) * (BB * HH) + n0M;
    load_t128(sbase + SM_BH, g_Bh + ((size_t)matM * HH + n0M) * HH + koffM);
    load_t128(sbase + SM_BL, g_Bl + ((size_t)matM * HH + n0M) * HH + koffM);

    // sub slices: units 148..159 split into 96 N=16 slices on CTAs 48..143 (warps 0..7)
    const bool hasSub = (cta >= 48 && cta < 144);
    int lS = 0;
    const __half* Asub = nullptr;
    float* dstS = nullptr;
    if (hasSub) {
        int j = cta - 48;
        int su = 148 + (j >> 3);
        int nsub = j & 7;
        int dS, ntS, kcS, matS, asS;
        decode(su, dS, lS, ntS, kcS, matS, asS);
        int koffS = (kcS & 3) * 128;
        int n0S = ntS * 128 + nsub * 16;
        Asub = g_hh + (size_t)(dS * 3 + asS) * BB * HH + koffS;
        dstS = g_pp + (size_t)((dS * 3 + lS) * 8 + kcS) * (BB * HH) + n0S;
        load_t16(sbase + SM_SBH, g_Bh + ((size_t)matS * HH + n0S) * HH + koffS);
        load_t16(sbase + SM_SBL, g_Bl + ((size_t)matS * HH + n0S) * HH + koffS);
    }

    // LN constants in smem (one task per LN CTA)
    float* lncb = (float*)(smem_raw + SM_LNC);
    float* lng  = lncb + HH;
    float* lnb  = lncb + 2 * HH;
    const int taskL = cta >> 4;
    const int ddL = (taskL >= 3) ? 1 : 0;
    const int llL = taskL - ddL * 3;
    if (isLN) {
        for (int i = tid; i < HH; i += 512) {
            lncb[i] = g_cb[taskL * HH + i];
            lng[i]  = ln_g[llL * HH + i];
            lnb[i]  = ln_b[llL * HH + i];
        }
    }
    __syncthreads();

    const int er = lane >> 2, ec = (lane & 3) * 2;
    // sub-slice lane components (warps 0..7, each 16 rows)
    const int ar2 = (wid << 4) + (lane & 15);
    const int aoff2 = ar2 * 256, aswz2 = ar2 & 7;
    const int nl2 = (lane & 7) + ((lane >> 4) << 3);
    const int boff2 = nl2 * 256, bswz2 = nl2 & 7;

    float acc[2][4][4];
    unsigned bt = 0;

    for (int s = 0; s < NSTEPS; s++) {
        const int tM = s - lM;
        const bool runM = (tM >= 0 && tM < TT);
        const int tS = s - lS;
        const bool runS = hasSub && (tS >= 0 && tS < TT) && (wid < 8);

        if (runM) load_t128(sbase + SM_A, Amain);
        if (hasSub && (tS >= 0 && tS < TT)) load_t128(sbase + SM_A2, Asub);
        __syncthreads();

        if (runM) {
#pragma unroll
            for (int mt = 0; mt < 2; mt++)
#pragma unroll
                for (int nt = 0; nt < 4; nt++)
#pragma unroll
                    for (int i = 0; i < 4; i++) acc[mt][nt][i] = 0.f;
#pragma unroll 2
            for (int ks = 0; ks < 8; ks++) {
                uint32_t a[2][4];
#pragma unroll
                for (int mt = 0; mt < 2; mt++) {
                    uint32_t addr = sbase + SM_A + aoff[mt] + ((uint32_t)((ks * 2 + ahi) ^ aswz[mt]) << 4);
                    LDSM4(a[mt][0], a[mt][1], a[mt][2], a[mt][3], addr);
                }
#pragma unroll
                for (int half = 0; half < 2; half++) {
                    uint32_t smB = sbase + (half ? SM_BL : SM_BH);
                    uint32_t bq[2][4];
#pragma unroll
                    for (int np = 0; np < 2; np++) {
                        uint32_t addr = smB + boff[np] + ((uint32_t)((ks * 2 + bhi) ^ bswz[np]) << 4);
                        LDSM4(bq[np][0], bq[np][1], bq[np][2], bq[np][3], addr);
                    }
#pragma unroll
                    for (int mt = 0; mt < 2; mt++)
#pragma unroll
                        for (int nt = 0; nt < 4; nt++) {
                            uint32_t b0 = bq[nt >> 1][(nt & 1) ? 2 : 0];
                            uint32_t b1 = bq[nt >> 1][(nt & 1) ? 3 : 1];
                            MMA_F16(acc[mt][nt], a[mt][0], a[mt][1], a[mt][2], a[mt][3], b0, b1);
                        }
                }
            }
#pragma unroll
            for (int mt = 0; mt < 2; mt++) {
                int row0 = wm * 32 + mt * 16 + er;
#pragma unroll
                for (int nt = 0; nt < 4; nt++) {
                    int col = wn * 32 + nt * 8 + ec;
                    __stcg((float2*)(dstM + (size_t)row0 * HH + col),
                           make_float2(acc[mt][nt][0], acc[mt][nt][1]));
                    __stcg((float2*)(dstM + (size_t)(row0 + 8) * HH + col),
                           make_float2(acc[mt][nt][2], acc[mt][nt][3]));
                }
            }
        }
        if (runS) {
            float accs[2][4];
#pragma unroll
            for (int nt = 0; nt < 2; nt++)
#pragma unroll
                for (int i = 0; i < 4; i++) accs[nt][i] = 0.f;
#pragma unroll 2
            for (int ks = 0; ks < 8; ks++) {
                uint32_t a2[4];
                uint32_t addr = sbase + SM_A2 + aoff2 + ((uint32_t)((ks * 2 + ahi) ^ aswz2) << 4);
                LDSM4(a2[0], a2[1], a2[2], a2[3], addr);
#pragma unroll
                for (int half = 0; half < 2; half++) {
                    uint32_t smB = sbase + (half ? SM_SBL : SM_SBH);
                    uint32_t bq[4];
                    uint32_t ba = smB + boff2 + ((uint32_t)((ks * 2 + bhi) ^ bswz2) << 4);
                    LDSM4(bq[0], bq[1], bq[2], bq[3], ba);
                    MMA_F16(accs[0], a2[0], a2[1], a2[2], a2[3], bq[0], bq[1]);
                    MMA_F16(accs[1], a2[0], a2[1], a2[2], a2[3], bq[2], bq[3]);
                }
            }
            int row0 = (wid << 4) + er;
#pragma unroll
            for (int nt = 0; nt < 2; nt++) {
                int col = nt * 8 + ec;
                __stcg((float2*)(dstS + (size_t)row0 * HH + col),
                       make_float2(accs[nt][0], accs[nt][1]));
                __stcg((float2*)(dstS + (size_t)(row0 + 8) * HH + col),
                       make_float2(accs[nt][2], accs[nt][3]));
            }
        }

        gsync_all(++bt, isLN);

        // ---- LN + tanh: warps 0..7, warp-per-row (96 CTAs x 8 = 768 rows) ----
        if (isLN && wid < 8) {
            const int b = ((cta << 3) + wid) & 127;
            const int tt2 = s - llL;
            if (tt2 >= 0 && tt2 < TT) {
                const int j0 = lane << 4;
                const float* ppb = g_pp + (size_t)taskL * 8 * (BB * HH) + (size_t)b * HH + j0;
                float4 v0 = ((const float4*)(lncb + j0))[0];
                float4 v1 = ((const float4*)(lncb + j0))[1];
                float4 v2 = ((const float4*)(lncb + j0))[2];
                float4 v3 = ((const float4*)(lncb + j0))[3];
                if (llL == 0) {
                    const float* x0p = g_X0 + ((size_t)(ddL * TT + tt2) * BB + b) * HH + j0;
                    {
                        float4 q0 = __ldg((const float4*)x0p);
                        float4 q1 = __ldg((const float4*)x0p + 1);
                        float4 q2 = __ldg((const float4*)x0p + 2);
                        float4 q3 = __ldg((const float4*)x0p + 3);
                        v0.x += q0.x; v0.y += q0.y; v0.z += q0.z; v0.w += q0.w;
                        v1.x += q1.x; v1.y += q1.y; v1.z += q1.z; v1.w += q1.w;
                        v2.x += q2.x; v2.y += q2.y; v2.z += q2.z; v2.w += q2.w;
                        v3.x += q3.x; v3.y += q3.y; v3.z += q3.z; v3.w += q3.w;
                    }
#pragma unroll
                    for (int c = 0; c < 4; c++) {
                        const float4* p4 = (const float4*)(ppb + (size_t)c * (BB * HH));
                        float4 q0 = __ldcg(p4), q1 = __ldcg(p4 + 1);
                        float4 q2 = __ldcg(p4 + 2), q3 = __ldcg(p4 + 3);
                        v0.x += q0.x; v0.y += q0.y; v0.z += q0.z; v0.w += q0.w;
                        v1.x += q1.x; v1.y += q1.y; v1.z += q1.z; v1.w += q1.w;
                        v2.x += q2.x; v2.y += q2.y; v2.z += q2.z; v2.w += q2.w;
                        v3.x += q3.x; v3.y += q3.y; v3.z += q3.z; v3.w += q3.w;
                    }
                } else {
#pragma unroll
                    for (int c = 0; c < 8; c++) {
                        const float4* p4 = (const float4*)(ppb + (size_t)c * (BB * HH));
                        float4 q0 = __ldcg(p4), q1 = __ldcg(p4 + 1);
                        float4 q2 = __ldcg(p4 + 2), q3 = __ldcg(p4 + 3);
                        v0.x += q0.x; v0.y += q0.y; v0.z += q0.z; v0.w += q0.w;
                        v1.x += q1.x; v1.y += q1.y; v1.z += q1.z; v1.w += q1.w;
                        v2.x += q2.x; v2.y += q2.y; v2.z += q2.z; v2.w += q2.w;
                        v3.x += q3.x; v3.y += q3.y; v3.z += q3.z; v3.w += q3.w;
                    }
                }
                float s1 = (v0.x + v0.y + v0.z + v0.w) + (v1.x + v1.y + v1.z + v1.w)
                         + (v2.x + v2.y + v2.z + v2.w) + (v3.x + v3.y + v3.z + v3.w);
                float s2 = (v0.x * v0.x + v0.y * v0.y + v0.z * v0.z + v0.w * v0.w)
                         + (v1.x * v1.x + v1.y * v1.y + v1.z * v1.z + v1.w * v1.w)
                         + (v2.x * v2.x + v2.y * v2.y + v2.z * v2.z + v2.w * v2.w)
                         + (v3.x * v3.x + v3.y * v3.y + v3.z * v3.z + v3.w * v3.w);
#pragma unroll
                for (int o = 16; o > 0; o >>= 1) {
                    s1 += __shfl_xor_sync(0xffffffffu, s1, o);
                    s2 += __shfl_xor_sync(0xffffffffu, s2, o);
                }
                const float mean = s1 * (1.f / HH);
                const float var  = s2 * (1.f / HH) - mean * mean;
                const float inv  = rsqrtf(var + LNEPS);
                const float4* gg = (const float4*)(lng + j0);
                const float4* bb = (const float4*)(lnb + j0);
                float hs[16];
#pragma unroll
                for (int q = 0; q < 4; q++) {
                    float4 vq = (q == 0) ? v0 : (q == 1) ? v1 : (q == 2) ? v2 : v3;
                    float4 g4 = gg[q], b4 = bb[q];
                    hs[q * 4 + 0] = tanhf((vq.x - mean) * inv * g4.x + b4.x);
                    hs[q * 4 + 1] = tanhf((vq.y - mean) * inv * g4.y + b4.y);
                    hs[q * 4 + 2] = tanhf((vq.z - mean) * inv * g4.z + b4.z);
                    hs[q * 4 + 3] = tanhf((vq.w - mean) * inv * g4.w + b4.w);
                }
                size_t hidx = (size_t)taskL * BB * HH + (size_t)b * HH + j0;
                uint4 u0, u1;
                {
                    __half2 p0 = __floats2half2_rn(hs[0], hs[1]);
                    __half2 p1 = __floats2half2_rn(hs[2], hs[3]);
                    __half2 p2 = __floats2half2_rn(hs[4], hs[5]);
                    __half2 p3 = __floats2half2_rn(hs[6], hs[7]);
                    u0.x = *(uint32_t*)&p0; u0.y = *(uint32_t*)&p1;
                    u0.z = *(uint32_t*)&p2; u0.w = *(uint32_t*)&p3;
                    __half2 p4 = __floats2half2_rn(hs[8], hs[9]);
                    __half2 p5 = __floats2half2_rn(hs[10], hs[11]);
                    __half2 p6 = __floats2half2_rn(hs[12], hs[13]);
                    __half2 p7 = __floats2half2_rn(hs[14], hs[15]);
                    u1.x = *(uint32_t*)&p4; u1.y = *(uint32_t*)&p5;
                    u1.z = *(uint32_t*)&p6; u1.w = *(uint32_t*)&p7;
                }
                __stcg((uint4*)(g_hh + hidx), u0);
                __stcg((uint4*)(g_hh + hidx) + 1, u1);
                if (llL == 2) {
                    float* o2p = g_o2 + ((size_t)(ddL * TT + tt2) * BB + b) * HH + j0;
#pragma unroll
                    for (int q = 0; q < 4; q++)
                        __stcg((float4*)o2p + q, make_float4(hs[q * 4 + 0], hs[q * 4 + 1],
                                                             hs[q * 4 + 2], hs[q * 4 + 3]));
                }
            }
        }

        gsync_ln(++bt, isLN);
    }
}

// ---------- X0 = Xh@(W0h+W0l) + Xl@W0h + b0   (fp16 3-product HMMA) ----------
__global__ void __launch_bounds__(256, 1) x0mma_kernel() {
    extern __shared__ char smem_raw[];
    const uint32_t sbase = smem_u32(smem_raw);
    const int tid = threadIdx.x;
    const int wid = tid >> 5, lane = tid & 31;
    const int wm = wid & 3, wn = wid >> 2;
    const int d = blockIdx.z;
    const int m0 = blockIdx.y * 128;
    const int n0 = blockIdx.x * 128;

    const __half* Ah = g_Xh + ((size_t)d * 32768 + m0) * 320;
    const __half* Al = g_Xl + ((size_t)d * 32768 + m0) * 320;
    const __half* Bh = g_W0h + ((size_t)d * HH + n0) * 320;
    const __half* Bl = g_W0l + ((size_t)d * HH + n0) * 320;

    int aoff[2], aswz[2];
#pragma unroll
    for (int mt = 0; mt < 2; mt++) {
        int r = wm * 32 + mt * 16 + (lane & 15);
        aoff[mt] = r * 128;
        aswz[mt] = r & 7;
    }
    const int ahi = lane >> 4;
    int boff[4], bswz[4];
#pragma unroll
    for (int np = 0; np < 4; np++) {
        int nl = wn * 64 + np * 16 + (lane & 7) + ((lane >> 4) << 3);
        boff[np] = nl * 128;
        bswz[np] = nl & 7;
    }
    const int bhi = (lane >> 3) & 1;

    float acc[2][8][4];
#pragma unroll
    for (int mt = 0; mt < 2; mt++)
#pragma unroll
        for (int nt = 0; nt < 8; nt++)
#pragma unroll
            for (int i = 0; i < 4; i++) acc[mt][nt][i] = 0.f;

    for (int kc = 0; kc < 5; kc++) {
        __syncthreads();
        load_t64(sbase + X0_AH, Ah + kc * 64);
        load_t64(sbase + X0_AL, Al + kc * 64);
        load_t64(sbase + X0_BH, Bh + kc * 64);
        load_t64(sbase + X0_BL, Bl + kc * 64);
        __syncthreads();
#pragma unroll
        for (int ks = 0; ks < 4; ks++) {
            uint32_t ah[2][4], al[2][4];
#pragma unroll
            for (int mt = 0; mt < 2; mt++) {
                uint32_t sw = (uint32_t)((ks * 2 + ahi) ^ aswz[mt]) << 4;
                LDSM4(ah[mt][0], ah[mt][1], ah[mt][2], ah[mt][3], sbase + X0_AH + aoff[mt] + sw);
                LDSM4(al[mt][0], al[mt][1], al[mt][2], al[mt][3], sbase + X0_AL + aoff[mt] + sw);
            }
            uint32_t bh[4][4], bl[4][4];
#pragma unroll
            for (int np = 0; np < 4; np++) {
                uint32_t sw = (uint32_t)((ks * 2 + bhi) ^ bswz[np]) << 4;
                LDSM4(bh[np][0], bh[np][1], bh[np][2], bh[np][3], sbase + X0_BH + boff[np] + sw);
                LDSM4(bl[np][0], bl[np][1], bl[np][2], bl[np][3], sbase + X0_BL + boff[np] + sw);
            }
#pragma unroll
            for (int mt = 0; mt < 2; mt++)
#pragma unroll
                for (int nt = 0; nt < 8; nt++) {
                    int q = nt >> 1;
                    int i0 = (nt & 1) ? 2 : 0, i1 = (nt & 1) ? 3 : 1;
                    MMA_F16(acc[mt][nt], ah[mt][0], ah[mt][1], ah[mt][2], ah[mt][3],
                            bh[q][i0], bh[q][i1]);
                    MMA_F16(acc[mt][nt], ah[mt][0], ah[mt][1], ah[mt][2], ah[mt][3],
                            bl[q][i0], bl[q][i1]);
                    MMA_F16(acc[mt][nt], al[mt][0], al[mt][1], al[mt][2], al[mt][3],
                            bh[q][i0], bh[q][i1]);
                }
        }
    }

    const int er = lane >> 2, ec = (lane & 3) * 2;
    const int b = m0 >> 8;
    const int tb = m0 & 255;
#pragma unroll
    for (int mt = 0; mt < 2; mt++) {
#pragma unroll
        for (int nt = 0; nt < 8; nt++) {
            int col = n0 + wn * 64 + nt * 8 + ec;
            float b0a = g_b0[d * HH + col];
            float b0b = g_b0[d * HH + col + 1];
#pragma unroll
            for (int rr = 0; rr < 2; rr++) {
                int rowin = wm * 32 + mt * 16 + er + rr * 8;
                int t = tb + rowin;
                float* dst = g_X0 + ((size_t)(d * TT + t) * BB + b) * HH + col;
                *(float2*)dst = make_float2(acc[mt][nt][rr * 2 + 0] + b0a,
                                            acc[mt][nt][rr * 2 + 1] + b0b);
            }
        }
    }
}

// ---------- gather + concat + FC ----------
__global__ void final_kernel(const int* __restrict__ pad,
                             const float* __restrict__ W_fc, const float* __restrict__ b_fc,
                             float* __restrict__ out) {
    __shared__ float cs[8][1024];
    const int sub  = threadIdx.x >> 6;
    const int lane = threadIdx.x & 63;
    const int r = blockIdx.x * 8 + sub;
    const int b = r >> 8;
    const int t = r & 255;
    const int p = pad[b];
    const int tt = (t < p) ? (p - t - 1) : t;
    const float* a0 = g_o2 + ((size_t)(0 * TT + t)  * BB + b) * HH;
    const float* a1 = g_o2 + ((size_t)(1 * TT + tt) * BB + b) * HH;
#pragma unroll
    for (int i = 0; i < 4; i++) {
        int j = lane * 4 + i * 256;
        float4 vv = (j < 512) ? *(const float4*)(a0 + j) : *(const float4*)(a1 + j - 512);
        *(float4*)(&cs[sub][j]) = vv;
    }
    __syncthreads();
    if (lane < NCLS) {
        float acc = b_fc[lane];
#pragma unroll 8
        for (int k = 0; k < 1024; k++) acc = fmaf(cs[sub][k], W_fc[k * NCLS + lane], acc);
        out[(size_t)r * NCLS + lane] = acc;
    }
}

// ---------- host launcher ----------
extern "C" void kernel_launch(void* const* d_in, const int* in_sizes, int n_in,
                              void* d_out, int out_size) {
    (void)in_sizes; (void)n_in; (void)out_size;
    const float* x      = (const float*)d_in[0];
    const float* rx     = (const float*)d_in[1];
    const int*   pad    = (const int*)  d_in[2];
    const float* W_emb  = (const float*)d_in[4];
    const float* b_emb  = (const float*)d_in[5];
    const float* Wx_l2r = (const float*)d_in[6];
    const float* bx_l2r = (const float*)d_in[7];
    const float* Wh_l2r = (const float*)d_in[8];
    const float* bh_l2r = (const float*)d_in[9];
    const float* Wx_r2l = (const float*)d_in[10];
    const float* bx_r2l = (const float*)d_in[11];
    const float* Wh_r2l = (const float*)d_in[12];
    const float* bh_r2l = (const float*)d_in[13];
    const float* ln_g   = (const float*)d_in[14];
    const float* ln_b   = (const float*)d_in[15];
    const float* W_fc   = (const float*)d_in[16];
    const float* b_fc   = (const float*)d_in[17];
    float* out = (float*)d_out;

    static int attr_done = 0;
    if (!attr_done) {
        cudaFuncSetAttribute(persist_kernel, cudaFuncAttributeMaxDynamicSharedMemorySize, DSMEM);
        cudaFuncSetAttribute(x0mma_kernel, cudaFuncAttributeMaxDynamicSharedMemorySize, X0_DS);
        attr_done = 1;
    }

    // launch order chosen so persist_kernel is the 4th launch (= ncu capture slot)
    prolog_a<<<8240, 256>>>(x, rx, W_emb, b_emb, Wx_l2r, bx_l2r, Wx_r2l, bx_r2l,
                            Wh_l2r, bh_l2r, Wh_r2l, bh_r2l);
    w0conv_kernel<<<dim3(16, 10, 2), dim3(32, 8)>>>();
    x0mma_kernel<<<dim3(4, 256, 2), 256, X0_DS>>>();

    persist_kernel<<<GRID_P, 512, DSMEM>>>(ln_g, ln_b);

    final_kernel<<<4096, 512>>>(pad, W_fc, b_fc, out);
}

// round 17
// speedup vs baseline: 1.4623x; 1.0685x over previous
#include <cuda_runtime.h>
#include <cuda_fp16.h>
#include <math.h>
#include <stdint.h>

#define BB    128
#define TT    256
#define INDIM 300
#define HH    512
#define NCLS  45
#define LNEPS 1e-5f

#define GRID_P  148
#define NSTEPS  258

// persist smem layout (byte offsets)
#define SM_BH   0
#define SM_BL   32768
#define SM_A    65536
#define SM_SBH  98304
#define SM_SBL  102400
#define SM_A2   106496
#define DSMEM   139264

// x0mma smem layout
#define X0_AH  0
#define X0_AL  16384
#define X0_BH  32768
#define X0_BL  49152
#define X0_DS  65536

// ---------- device scratch ----------
__device__ float g_W0[2 * INDIM * HH];
__device__ float g_b0[2 * HH];
__device__ __align__(16) __half g_W0h[2 * HH * 320];        // [d][n][k320]
__device__ __align__(16) __half g_W0l[2 * HH * 320];
__device__ __align__(16) __half g_Xh[2 * 32768 * 320];      // [d][m][k320]
__device__ __align__(16) __half g_Xl[2 * 32768 * 320];
__device__ float g_X0[2 * TT * BB * HH];
__device__ __align__(16) __half g_Bh[10 * HH * HH];         // [mat][n][k512] hi
__device__ __align__(16) __half g_Bl[10 * HH * HH];         // lo
__device__ __align__(16) __half g_hh[2 * 3 * BB * HH];      // h fp16
__device__ float g_pp[2 * 3 * 8 * BB * HH];                 // slots (d*3+l)*8+kc
__device__ float g_o2[2 * TT * BB * HH];
__device__ float g_cb[6 * HH];
__device__ unsigned g_barc;                                  // barrier A counter
__device__ unsigned g_sense;                                 // barrier A epoch
__device__ unsigned g_barc2;                                 // barrier B counter
__device__ unsigned g_sense2;                                // barrier B epoch

// ---------- helpers ----------
__device__ __forceinline__ uint32_t smem_u32(const void* p) {
    uint32_t a;
    asm("{ .reg .u64 t; cvta.to.shared.u64 t, %1; cvt.u32.u64 %0, t; }" : "=r"(a) : "l"(p));
    return a;
}

// symmetric sense-reversing barrier (R10/R13 proven core). No CCTL: all
// cross-CTA data moves .cg (L2-only); acq_rel/acquire order it.
__device__ __forceinline__ void gsyncA(unsigned target) {
    __syncthreads();
    if (threadIdx.x == 0) {
        unsigned old;
        asm volatile("atom.add.acq_rel.gpu.u32 %0, [%1], 1;" : "=r"(old) : "l"(&g_barc) : "memory");
        if (old == (unsigned)(GRID_P - 1)) {
            asm volatile("st.relaxed.gpu.u32 [%0], 0;" :: "l"(&g_barc) : "memory");
            asm volatile("st.release.gpu.u32 [%0], %1;" :: "l"(&g_sense), "r"(target) : "memory");
        } else {
            unsigned sv;
            do {
                asm volatile("ld.acquire.gpu.u32 %0, [%1];" : "=r"(sv) : "l"(&g_sense) : "memory");
            } while (sv < target);
        }
    }
    __syncthreads();
}
__device__ __forceinline__ void gsyncB(unsigned target) {
    __syncthreads();
    if (threadIdx.x == 0) {
        unsigned old;
        asm volatile("atom.add.acq_rel.gpu.u32 %0, [%1], 1;" : "=r"(old) : "l"(&g_barc2) : "memory");
        if (old == (unsigned)(GRID_P - 1)) {
            asm volatile("st.relaxed.gpu.u32 [%0], 0;" :: "l"(&g_barc2) : "memory");
            asm volatile("st.release.gpu.u32 [%0], %1;" :: "l"(&g_sense2), "r"(target) : "memory");
        } else {
            unsigned sv;
            do {
                asm volatile("ld.acquire.gpu.u32 %0, [%1];" : "=r"(sv) : "l"(&g_sense2) : "memory");
            } while (sv < target);
        }
    }
    __syncthreads();
}

// ---------- fused prologue A: w0 GEMM + init + xconv + convw ----------
// grid: [0,48) w0 | [48,1584) init | [1584,5680) xconv | [5680,8240) convw
__global__ void __launch_bounds__(256)
prolog_a(const float* __restrict__ x, const float* __restrict__ rx,
         const float* __restrict__ W_emb, const float* __restrict__ b_emb,
         const float* __restrict__ Wx_l2r, const float* __restrict__ bx_l2r,
         const float* __restrict__ Wx_r2l, const float* __restrict__ bx_r2l,
         const float* __restrict__ Wh_l2r, const float* __restrict__ bh_l2r,
         const float* __restrict__ Wh_r2l, const float* __restrict__ bh_r2l) {
    __shared__ float shf[16 * 136 + 16 * 64];
    const int blk = blockIdx.x;
    const int tid = threadIdx.x;

    if (blk < 48) {
        const int d = blk / 24;
        const int m0 = ((blk % 24) / 8) * 128;
        const int n0 = (blk % 8) * 64;
        const float* Wx0 = d ? Wx_r2l : Wx_l2r;
        const float* bx0 = d ? bx_r2l : bx_l2r;
        float (*As)[136] = (float(*)[136])shf;
        float (*Bs)[64]  = (float(*)[64])(shf + 16 * 136);
        const int ty = tid >> 4, tx = tid & 15;
        float acc[8][4];
#pragma unroll
        for (int i = 0; i < 8; i++)
#pragma unroll
            for (int j = 0; j < 4; j++) acc[i][j] = 0.f;

        for (int k0 = 0; k0 < HH; k0 += 16) {
            {
                const int row = tid >> 2, c4 = (tid & 3) * 4;
#pragma unroll
                for (int rr = 0; rr < 2; rr++) {
                    int r = row + rr * 64;
                    int gm = m0 + r;
                    float4 av = make_float4(0.f, 0.f, 0.f, 0.f);
                    if (gm < INDIM)       av = *(const float4*)(W_emb + (size_t)gm * HH + k0 + c4);
                    else if (gm == INDIM) av = *(const float4*)(b_emb + k0 + c4);
                    As[c4 + 0][r] = av.x; As[c4 + 1][r] = av.y;
                    As[c4 + 2][r] = av.z; As[c4 + 3][r] = av.w;
                }
            }
            {
                const int row = tid >> 4, c4 = (tid & 15) * 4;
                float4 bv = *(const float4*)(Wx0 + (size_t)(k0 + row) * HH + n0 + c4);
                *(float4*)(&Bs[row][c4]) = bv;
            }
            __syncthreads();
#pragma unroll
            for (int kk = 0; kk < 16; kk++) {
                float4 a0 = *(const float4*)(&As[kk][ty * 8]);
                float4 a1 = *(const float4*)(&As[kk][ty * 8 + 4]);
                float4 b4 = *(const float4*)(&Bs[kk][tx * 4]);
                float a[8] = {a0.x, a0.y, a0.z, a0.w, a1.x, a1.y, a1.z, a1.w};
                float b[4] = {b4.x, b4.y, b4.z, b4.w};
#pragma unroll
                for (int i = 0; i < 8; i++)
#pragma unroll
                    for (int j = 0; j < 4; j++) acc[i][j] = fmaf(a[i], b[j], acc[i][j]);
            }
            __syncthreads();
        }
#pragma unroll
        for (int i = 0; i < 8; i++) {
            int gm = m0 + ty * 8 + i;
            int gn = n0 + tx * 4;
            if (gm < INDIM) {
#pragma unroll
                for (int j = 0; j < 4; j++) g_W0[(size_t)(d * INDIM + gm) * HH + gn + j] = acc[i][j];
            } else if (gm == INDIM) {
#pragma unroll
                for (int j = 0; j < 4; j++) g_b0[d * HH + gn + j] = acc[i][j] + bx0[gn + j];
            }
        }
    } else if (blk < 1584) {
        int i = (blk - 48) * 256 + tid;
        if (i == 0) { g_barc = 0; g_sense = 0; g_barc2 = 0; g_sense2 = 0; }
        if (i < 2 * 3 * BB * HH) g_hh[i] = __float2half(0.f);
        if (i < 6 * HH) {
            int task = i / HH, j = i % HH;
            int dd = task / 3, ll = task - dd * 3;
            const float* bx = dd ? bx_r2l : bx_l2r;
            const float* bh = dd ? bh_r2l : bh_l2r;
            float cb = bh[ll * HH + j];
            if (ll != 0) cb += bx[ll * HH + j];
            g_cb[i] = cb;
        }
    } else if (blk < 5680) {
        const int bx = blk - 1584;
        const int row = bx * 16 + (tid >> 4);
        const int d = row >> 15;
        const int m = row & 32767;
        const float* src = d ? rx : x;
        const float2* s2 = (const float2*)(src + (size_t)m * INDIM);
        __half2* dh = (__half2*)g_Xh + (size_t)row * 160;
        __half2* dl = (__half2*)g_Xl + (size_t)row * 160;
#pragma unroll
        for (int k = 0; k < 10; k++) {
            int c2 = (tid & 15) + 16 * k;
            float2 v = (c2 < 150) ? s2[c2] : make_float2(0.f, 0.f);
            __half hx = __float2half(v.x), hy = __float2half(v.y);
            __half lx = __float2half(v.x - __half2float(hx));
            __half ly = __float2half(v.y - __half2float(hy));
            dh[c2] = __halves2half2(hx, hy);
            dl[c2] = __halves2half2(lx, ly);
        }
    } else {
        const int c = blk - 5680;
        const int mat = c / 256;
        const int rem = c % 256;
        const int k0 = (rem / 16) * 32, n0 = (rem % 16) * 32;
        const int d = mat / 5, mm = mat % 5;
        const float* Wx = d ? Wx_r2l : Wx_l2r;
        const float* Wh = d ? Wh_r2l : Wh_l2r;
        const float* W;
        if      (mm == 0) W = Wh;
        else if (mm == 1) W = Wx + (size_t)1 * HH * HH;
        else if (mm == 2) W = Wh + (size_t)1 * HH * HH;
        else if (mm == 3) W = Wx + (size_t)2 * HH * HH;
        else              W = Wh + (size_t)2 * HH * HH;
        float (*tile)[33] = (float(*)[33])shf;
        const int tx = tid & 31, ty = tid >> 5;
        for (int r = ty; r < 32; r += 8)
            tile[r][tx] = W[(size_t)(k0 + r) * HH + n0 + tx];
        __syncthreads();
        for (int r = ty; r < 32; r += 8) {
            float v = tile[tx][r];
            __half hi = __float2half(v);
            __half lo = __float2half(v - __half2float(hi));
            size_t dst = ((size_t)mat * HH + n0 + r) * HH + k0 + tx;
            g_Bh[dst] = hi;
            g_Bl[dst] = lo;
        }
    }
}

// ---------- W0 fp32 [d][k300][n] -> fp16 hi/lo transposed [d][n][k320] ----------
__global__ void w0conv_kernel() {
    __shared__ float tile[32][33];
    const int d = blockIdx.z;
    const int k0 = blockIdx.y * 32, n0 = blockIdx.x * 32;
    const int tx = threadIdx.x;
    for (int r = threadIdx.y; r < 32; r += 8) {
        int k = k0 + r;
        tile[r][tx] = (k < INDIM) ? g_W0[(size_t)(d * INDIM + k) * HH + n0 + tx] : 0.f;
    }
    __syncthreads();
    for (int r = threadIdx.y; r < 32; r += 8) {
        float v = tile[tx][r];
        __half hi = __float2half(v);
        __half lo = __float2half(v - __half2float(hi));
        size_t dst = ((size_t)d * HH + n0 + r) * 320 + k0 + tx;
        g_W0h[dst] = hi;
        g_W0l[dst] = lo;
    }
}

// ---------- smem tile loaders (16B-chunk XOR swizzle); L2-only loads ----------
// 128 rows x 128 halfs, 512 threads
__device__ __forceinline__ void load_t128(uint32_t dst, const __half* __restrict__ src) {
    const int tid = threadIdx.x;
#pragma unroll
    for (int it = 0; it < 4; it++) {
        int idx = it * 512 + tid;
        int r = idx >> 4, c = idx & 15;
        uint4 v = __ldcg((const uint4*)(src + (size_t)r * 512 + c * 8));
        uint32_t a = dst + r * 256 + (((uint32_t)(c ^ (r & 7))) << 4);
        asm volatile("st.shared.v4.b32 [%0], {%1,%2,%3,%4};"
                     :: "r"(a), "r"(v.x), "r"(v.y), "r"(v.z), "r"(v.w) : "memory");
    }
}
// 16 rows x 128 halfs, 512 threads (first 256 act)
__device__ __forceinline__ void load_t16(uint32_t dst, const __half* __restrict__ src) {
    const int tid = threadIdx.x;
    if (tid < 256) {
        int r = tid >> 4, c = tid & 15;
        uint4 v = __ldcg((const uint4*)(src + (size_t)r * 512 + c * 8));
        uint32_t a = dst + r * 256 + (((uint32_t)(c ^ (r & 7))) << 4);
        asm volatile("st.shared.v4.b32 [%0], {%1,%2,%3,%4};"
                     :: "r"(a), "r"(v.x), "r"(v.y), "r"(v.z), "r"(v.w) : "memory");
    }
}
// 128 rows x 64 halfs, src row stride 320 halfs, 512 threads (x0mma)
__device__ __forceinline__ void load_t64(uint32_t dst, const __half* __restrict__ src) {
    const int tid = threadIdx.x;
#pragma unroll
    for (int it = 0; it < 2; it++) {
        int idx = it * 512 + tid;
        int r = idx >> 3, c = idx & 7;
        uint4 v = *(const uint4*)(src + (size_t)r * 320 + c * 8);
        uint32_t a = dst + r * 128 + (((uint32_t)(c ^ (r & 7))) << 4);
        asm volatile("st.shared.v4.b32 [%0], {%1,%2,%3,%4};"
                     :: "r"(a), "r"(v.x), "r"(v.y), "r"(v.z), "r"(v.w) : "memory");
    }
}

#define MMA_F16(acc, a0, a1, a2, a3, b0, b1) \
    asm volatile( \
        "mma.sync.aligned.m16n8k16.row.col.f32.f16.f16.f32 " \
        "{%0,%1,%2,%3}, {%4,%5,%6,%7}, {%8,%9}, {%0,%1,%2,%3};" \
        : "+f"((acc)[0]), "+f"((acc)[1]), "+f"((acc)[2]), "+f"((acc)[3]) \
        : "r"(a0), "r"(a1), "r"(a2), "r"(a3), "r"(b0), "r"(b1))

#define LDSM4(r0, r1, r2, r3, addr) \
    asm volatile("ldmatrix.sync.aligned.m8n8.x4.shared.b16 {%0,%1,%2,%3}, [%4];" \
                 : "=r"(r0), "=r"(r1), "=r"(r2), "=r"(r3) : "r"(addr))

// ---------- persistent wavefront kernel (512 threads, warp tile 32x32) ----------
__global__ void __launch_bounds__(512, 1)
persist_kernel(const float* __restrict__ ln_g, const float* __restrict__ ln_b) {
    extern __shared__ char smem_raw[];
    const uint32_t sbase = smem_u32(smem_raw);
    const int tid = threadIdx.x;
    const int wid = tid >> 5, lane = tid & 31;
    const int wm = wid & 3, wn = wid >> 2;   // 4 x 4 warp grid

    int aoff[2], aswz[2];
#pragma unroll
    for (int mt = 0; mt < 2; mt++) {
        int r = wm * 32 + mt * 16 + (lane & 15);
        aoff[mt] = r * 256;
        aswz[mt] = r & 7;
    }
    const int ahi = lane >> 4;
    int boff[2], bswz[2];
#pragma unroll
    for (int np = 0; np < 2; np++) {
        int nl = wn * 32 + np * 16 + (lane & 7) + ((lane >> 4) << 3);
        boff[np] = nl * 256;
        bswz[np] = nl & 7;
    }
    const int bhi = (lane >> 3) & 1;

    auto decode = [](int u, int& d, int& l, int& ntile, int& kc, int& mat, int& asrc) {
        d = u / 80;
        int r = u % 80;
        if (r < 16)      { l = 0; ntile = r >> 2;        kc = r & 3;
                           mat = d * 5 + 0; asrc = 0; }
        else if (r < 48) { l = 1; int rr = r - 16; ntile = rr >> 3; kc = rr & 7;
                           if (kc < 4) { mat = d * 5 + 1; asrc = 0; }
                           else        { mat = d * 5 + 2; asrc = 1; } }
        else             { l = 2; int rr = r - 48; ntile = rr >> 3; kc = rr & 7;
                           if (kc < 4) { mat = d * 5 + 3; asrc = 1; }
                           else        { mat = d * 5 + 4; asrc = 2; } }
    };

    const int cta = blockIdx.x;

    int dM, lM, ntM, kcM, matM, asM;
    decode(cta, dM, lM, ntM, kcM, matM, asM);
    const int koffM = (kcM & 3) * 128;
    const int n0M = ntM * 128;
    const __half* Amain = g_hh + (size_t)(dM * 3 + asM) * BB * HH + koffM;
    float* dstM = g_pp + (size_t)((dM * 3 + lM) * 8 + kcM) * (BB * HH) + n0M;
    load_t128(sbase + SM_BH, g_Bh + ((size_t)matM * HH + n0M) * HH + koffM);
    load_t128(sbase + SM_BL, g_Bl + ((size_t)matM * HH + n0M) * HH + koffM);

    // sub slices: units 148..159 split into 96 N=16 slices on CTAs 48..143 (warps 0..7)
    const bool hasSub = (cta >= 48 && cta < 144);
    int lS = 0;
    const __half* Asub = nullptr;
    float* dstS = nullptr;
    if (hasSub) {
        int j = cta - 48;
        int su = 148 + (j >> 3);
        int nsub = j & 7;
        int dS, ntS, kcS, matS, asS;
        decode(su, dS, lS, ntS, kcS, matS, asS);
        int koffS = (kcS & 3) * 128;
        int n0S = ntS * 128 + nsub * 16;
        Asub = g_hh + (size_t)(dS * 3 + asS) * BB * HH + koffS;
        dstS = g_pp + (size_t)((dS * 3 + lS) * 8 + kcS) * (BB * HH) + n0S;
        load_t16(sbase + SM_SBH, g_Bh + ((size_t)matS * HH + n0S) * HH + koffS);
        load_t16(sbase + SM_SBL, g_Bl + ((size_t)matS * HH + n0S) * HH + koffS);
    }
    __syncthreads();

    const int er = lane >> 2, ec = (lane & 3) * 2;
    const int ar2 = (wid << 4) + (lane & 15);
    const int aoff2 = ar2 * 256, aswz2 = ar2 & 7;
    const int nl2 = (lane & 7) + ((lane >> 4) << 3);
    const int boff2 = nl2 * 256, bswz2 = nl2 & 7;

    // LN row assignment: warp wid handles row = cta + 148*wid (one row max)
    const int rowL = cta + 148 * wid;
    const bool hasLN = (wid < 6) && (rowL < 768);
    const int taskL = rowL >> 7;
    const int bL = rowL & 127;
    const int ddL = (taskL >= 3) ? 1 : 0;
    const int llL = taskL - ddL * 3;

    float acc[2][4][4];
    unsigned bt = 0;

    for (int s = 0; s < NSTEPS; s++) {
        const int tM = s - lM;
        const bool runM = (tM >= 0 && tM < TT);
        const int tS = s - lS;
        const bool runS = hasSub && (tS >= 0 && tS < TT) && (wid < 8);

        if (runM) load_t128(sbase + SM_A, Amain);
        if (hasSub && (tS >= 0 && tS < TT)) load_t128(sbase + SM_A2, Asub);
        __syncthreads();

        if (runM) {
#pragma unroll
            for (int mt = 0; mt < 2; mt++)
#pragma unroll
                for (int nt = 0; nt < 4; nt++)
#pragma unroll
                    for (int i = 0; i < 4; i++) acc[mt][nt][i] = 0.f;
#pragma unroll 2
            for (int ks = 0; ks < 8; ks++) {
                uint32_t a[2][4];
#pragma unroll
                for (int mt = 0; mt < 2; mt++) {
                    uint32_t addr = sbase + SM_A + aoff[mt] + ((uint32_t)((ks * 2 + ahi) ^ aswz[mt]) << 4);
                    LDSM4(a[mt][0], a[mt][1], a[mt][2], a[mt][3], addr);
                }
#pragma unroll
                for (int half = 0; half < 2; half++) {
                    uint32_t smB = sbase + (half ? SM_BL : SM_BH);
                    uint32_t bq[2][4];
#pragma unroll
                    for (int np = 0; np < 2; np++) {
                        uint32_t addr = smB + boff[np] + ((uint32_t)((ks * 2 + bhi) ^ bswz[np]) << 4);
                        LDSM4(bq[np][0], bq[np][1], bq[np][2], bq[np][3], addr);
                    }
#pragma unroll
                    for (int mt = 0; mt < 2; mt++)
#pragma unroll
                        for (int nt = 0; nt < 4; nt++) {
                            uint32_t b0 = bq[nt >> 1][(nt & 1) ? 2 : 0];
                            uint32_t b1 = bq[nt >> 1][(nt & 1) ? 3 : 1];
                            MMA_F16(acc[mt][nt], a[mt][0], a[mt][1], a[mt][2], a[mt][3], b0, b1);
                        }
                }
            }
#pragma unroll
            for (int mt = 0; mt < 2; mt++) {
                int row0 = wm * 32 + mt * 16 + er;
#pragma unroll
                for (int nt = 0; nt < 4; nt++) {
                    int col = wn * 32 + nt * 8 + ec;
                    __stcg((float2*)(dstM + (size_t)row0 * HH + col),
                           make_float2(acc[mt][nt][0], acc[mt][nt][1]));
                    __stcg((float2*)(dstM + (size_t)(row0 + 8) * HH + col),
                           make_float2(acc[mt][nt][2], acc[mt][nt][3]));
                }
            }
        }
        if (runS) {
            float accs[2][4];
#pragma unroll
            for (int nt = 0; nt < 2; nt++)
#pragma unroll
                for (int i = 0; i < 4; i++) accs[nt][i] = 0.f;
#pragma unroll 2
            for (int ks = 0; ks < 8; ks++) {
                uint32_t a2[4];
                uint32_t addr = sbase + SM_A2 + aoff2 + ((uint32_t)((ks * 2 + ahi) ^ aswz2) << 4);
                LDSM4(a2[0], a2[1], a2[2], a2[3], addr);
#pragma unroll
                for (int half = 0; half < 2; half++) {
                    uint32_t smB = sbase + (half ? SM_SBL : SM_SBH);
                    uint32_t bq[4];
                    uint32_t ba = smB + boff2 + ((uint32_t)((ks * 2 + bhi) ^ bswz2) << 4);
                    LDSM4(bq[0], bq[1], bq[2], bq[3], ba);
                    MMA_F16(accs[0], a2[0], a2[1], a2[2], a2[3], bq[0], bq[1]);
                    MMA_F16(accs[1], a2[0], a2[1], a2[2], a2[3], bq[2], bq[3]);
                }
            }
            int row0 = (wid << 4) + er;
#pragma unroll
            for (int nt = 0; nt < 2; nt++) {
                int col = nt * 8 + ec;
                __stcg((float2*)(dstS + (size_t)row0 * HH + col),
                       make_float2(accs[nt][0], accs[nt][1]));
                __stcg((float2*)(dstS + (size_t)(row0 + 8) * HH + col),
                       make_float2(accs[nt][2], accs[nt][3]));
            }
        }

        gsyncA(++bt);

        // ---- LN + tanh: warp-per-row, spread over all 148 CTAs ----
        if (hasLN) {
            const int tt2 = s - llL;
            if (tt2 >= 0 && tt2 < TT) {
                const int j0 = lane << 4;
                const float* ppb = g_pp + (size_t)taskL * 8 * (BB * HH) + (size_t)bL * HH + j0;
                const float* cbp = g_cb + taskL * HH + j0;
                float4 v0 = __ldg((const float4*)cbp);
                float4 v1 = __ldg((const float4*)cbp + 1);
                float4 v2 = __ldg((const float4*)cbp + 2);
                float4 v3 = __ldg((const float4*)cbp + 3);
                if (llL == 0) {
                    const float* x0p = g_X0 + ((size_t)(ddL * TT + tt2) * BB + bL) * HH + j0;
                    {
                        float4 q0 = __ldcg((const float4*)x0p);
                        float4 q1 = __ldcg((const float4*)x0p + 1);
                        float4 q2 = __ldcg((const float4*)x0p + 2);
                        float4 q3 = __ldcg((const float4*)x0p + 3);
                        v0.x += q0.x; v0.y += q0.y; v0.z += q0.z; v0.w += q0.w;
                        v1.x += q1.x; v1.y += q1.y; v1.z += q1.z; v1.w += q1.w;
                        v2.x += q2.x; v2.y += q2.y; v2.z += q2.z; v2.w += q2.w;
                        v3.x += q3.x; v3.y += q3.y; v3.z += q3.z; v3.w += q3.w;
                    }
#pragma unroll
                    for (int c = 0; c < 4; c++) {
                        const float4* p4 = (const float4*)(ppb + (size_t)c * (BB * HH));
                        float4 q0 = __ldcg(p4), q1 = __ldcg(p4 + 1);
                        float4 q2 = __ldcg(p4 + 2), q3 = __ldcg(p4 + 3);
                        v0.x += q0.x; v0.y += q0.y; v0.z += q0.z; v0.w += q0.w;
                        v1.x += q1.x; v1.y += q1.y; v1.z += q1.z; v1.w += q1.w;
                        v2.x += q2.x; v2.y += q2.y; v2.z += q2.z; v2.w += q2.w;
                        v3.x += q3.x; v3.y += q3.y; v3.z += q3.z; v3.w += q3.w;
                    }
                } else {
#pragma unroll
                    for (int c = 0; c < 8; c++) {
                        const float4* p4 = (const float4*)(ppb + (size_t)c * (BB * HH));
                        float4 q0 = __ldcg(p4), q1 = __ldcg(p4 + 1);
                        float4 q2 = __ldcg(p4 + 2), q3 = __ldcg(p4 + 3);
                        v0.x += q0.x; v0.y += q0.y; v0.z += q0.z; v0.w += q0.w;
                        v1.x += q1.x; v1.y += q1.y; v1.z += q1.z; v1.w += q1.w;
                        v2.x += q2.x; v2.y += q2.y; v2.z += q2.z; v2.w += q2.w;
                        v3.x += q3.x; v3.y += q3.y; v3.z += q3.z; v3.w += q3.w;
                    }
                }
                float s1 = (v0.x + v0.y + v0.z + v0.w) + (v1.x + v1.y + v1.z + v1.w)
                         + (v2.x + v2.y + v2.z + v2.w) + (v3.x + v3.y + v3.z + v3.w);
                float s2 = (v0.x * v0.x + v0.y * v0.y + v0.z * v0.z + v0.w * v0.w)
                         + (v1.x * v1.x + v1.y * v1.y + v1.z * v1.z + v1.w * v1.w)
                         + (v2.x * v2.x + v2.y * v2.y + v2.z * v2.z + v2.w * v2.w)
                         + (v3.x * v3.x + v3.y * v3.y + v3.z * v3.z + v3.w * v3.w);
#pragma unroll
                for (int o = 16; o > 0; o >>= 1) {
                    s1 += __shfl_xor_sync(0xffffffffu, s1, o);
                    s2 += __shfl_xor_sync(0xffffffffu, s2, o);
                }
                const float mean = s1 * (1.f / HH);
                const float var  = s2 * (1.f / HH) - mean * mean;
                const float inv  = rsqrtf(var + LNEPS);
                const float4* gg = (const float4*)(ln_g + llL * HH + j0);
                const float4* bb = (const float4*)(ln_b + llL * HH + j0);
                float hs[16];
#pragma unroll
                for (int q = 0; q < 4; q++) {
                    float4 vq = (q == 0) ? v0 : (q == 1) ? v1 : (q == 2) ? v2 : v3;
                    float4 g4 = __ldg(gg + q), b4 = __ldg(bb + q);
                    hs[q * 4 + 0] = tanhf((vq.x - mean) * inv * g4.x + b4.x);
                    hs[q * 4 + 1] = tanhf((vq.y - mean) * inv * g4.y + b4.y);
                    hs[q * 4 + 2] = tanhf((vq.z - mean) * inv * g4.z + b4.z);
                    hs[q * 4 + 3] = tanhf((vq.w - mean) * inv * g4.w + b4.w);
                }
                size_t hidx = (size_t)taskL * BB * HH + (size_t)bL * HH + j0;
                uint4 u0, u1;
                {
                    __half2 p0 = __floats2half2_rn(hs[0], hs[1]);
                    __half2 p1 = __floats2half2_rn(hs[2], hs[3]);
                    __half2 p2 = __floats2half2_rn(hs[4], hs[5]);
                    __half2 p3 = __floats2half2_rn(hs[6], hs[7]);
                    u0.x = *(uint32_t*)&p0; u0.y = *(uint32_t*)&p1;
                    u0.z = *(uint32_t*)&p2; u0.w = *(uint32_t*)&p3;
                    __half2 p4 = __floats2half2_rn(hs[8], hs[9]);
                    __half2 p5 = __floats2half2_rn(hs[10], hs[11]);
                    __half2 p6 = __floats2half2_rn(hs[12], hs[13]);
                    __half2 p7 = __floats2half2_rn(hs[14], hs[15]);
                    u1.x = *(uint32_t*)&p4; u1.y = *(uint32_t*)&p5;
                    u1.z = *(uint32_t*)&p6; u1.w = *(uint32_t*)&p7;
                }
                __stcg((uint4*)(g_hh + hidx), u0);
                __stcg((uint4*)(g_hh + hidx) + 1, u1);
                if (llL == 2) {
                    float* o2p = g_o2 + ((size_t)(ddL * TT + tt2) * BB + bL) * HH + j0;
#pragma unroll
                    for (int q = 0; q < 4; q++)
                        __stcg((float4*)o2p + q, make_float4(hs[q * 4 + 0], hs[q * 4 + 1],
                                                             hs[q * 4 + 2], hs[q * 4 + 3]));
                }
            }
        }

        gsyncB(++bt);
    }
}

// ---------- X0 = Xh@(W0h+W0l) + Xl@W0h + b0  (512 threads, 32x32 warp tile) ----------
__global__ void __launch_bounds__(512, 1) x0mma_kernel() {
    extern __shared__ char smem_raw[];
    const uint32_t sbase = smem_u32(smem_raw);
    const int tid = threadIdx.x;
    const int wid = tid >> 5, lane = tid & 31;
    const int wm = wid & 3, wn = wid >> 2;   // 4x4 warp grid
    const int d = blockIdx.z;
    const int m0 = blockIdx.y * 128;
    const int n0 = blockIdx.x * 128;

    const __half* Ah = g_Xh + ((size_t)d * 32768 + m0) * 320;
    const __half* Al = g_Xl + ((size_t)d * 32768 + m0) * 320;
    const __half* Bh = g_W0h + ((size_t)d * HH + n0) * 320;
    const __half* Bl = g_W0l + ((size_t)d * HH + n0) * 320;

    int aoff[2], aswz[2];
#pragma unroll
    for (int mt = 0; mt < 2; mt++) {
        int r = wm * 32 + mt * 16 + (lane & 15);
        aoff[mt] = r * 128;
        aswz[mt] = r & 7;
    }
    const int ahi = lane >> 4;
    int boff[2], bswz[2];
#pragma unroll
    for (int np = 0; np < 2; np++) {
        int nl = wn * 32 + np * 16 + (lane & 7) + ((lane >> 4) << 3);
        boff[np] = nl * 128;
        bswz[np] = nl & 7;
    }
    const int bhi = (lane >> 3) & 1;

    float acc[2][4][4];
#pragma unroll
    for (int mt = 0; mt < 2; mt++)
#pragma unroll
        for (int nt = 0; nt < 4; nt++)
#pragma unroll
            for (int i = 0; i < 4; i++) acc[mt][nt][i] = 0.f;

    for (int kc = 0; kc < 5; kc++) {
        __syncthreads();
        load_t64(sbase + X0_AH, Ah + kc * 64);
        load_t64(sbase + X0_AL, Al + kc * 64);
        load_t64(sbase + X0_BH, Bh + kc * 64);
        load_t64(sbase + X0_BL, Bl + kc * 64);
        __syncthreads();
#pragma unroll
        for (int ks = 0; ks < 4; ks++) {
            uint32_t ah[2][4], al[2][4];
#pragma unroll
            for (int mt = 0; mt < 2; mt++) {
                uint32_t sw = (uint32_t)((ks * 2 + ahi) ^ aswz[mt]) << 4;
                LDSM4(ah[mt][0], ah[mt][1], ah[mt][2], ah[mt][3], sbase + X0_AH + aoff[mt] + sw);
                LDSM4(al[mt][0], al[mt][1], al[mt][2], al[mt][3], sbase + X0_AL + aoff[mt] + sw);
            }
            uint32_t bh[2][4], bl[2][4];
#pragma unroll
            for (int np = 0; np < 2; np++) {
                uint32_t sw = (uint32_t)((ks * 2 + bhi) ^ bswz[np]) << 4;
                LDSM4(bh[np][0], bh[np][1], bh[np][2], bh[np][3], sbase + X0_BH + boff[np] + sw);
                LDSM4(bl[np][0], bl[np][1], bl[np][2], bl[np][3], sbase + X0_BL + boff[np] + sw);
            }
#pragma unroll
            for (int mt = 0; mt < 2; mt++)
#pragma unroll
                for (int nt = 0; nt < 4; nt++) {
                    int q = nt >> 1;
                    int i0 = (nt & 1) ? 2 : 0, i1 = (nt & 1) ? 3 : 1;
                    MMA_F16(acc[mt][nt], ah[mt][0], ah[mt][1], ah[mt][2], ah[mt][3],
                            bh[q][i0], bh[q][i1]);
                    MMA_F16(acc[mt][nt], ah[mt][0], ah[mt][1], ah[mt][2], ah[mt][3],
                            bl[q][i0], bl[q][i1]);
                    MMA_F16(acc[mt][nt], al[mt][0], al[mt][1], al[mt][2], al[mt][3],
                            bh[q][i0], bh[q][i1]);
                }
        }
    }

    const int er = lane >> 2, ec = (lane & 3) * 2;
    const int b = m0 >> 8;
    const int tb = m0 & 255;
#pragma unroll
    for (int mt = 0; mt < 2; mt++) {
#pragma unroll
        for (int nt = 0; nt < 4; nt++) {
            int col = n0 + wn * 32 + nt * 8 + ec;
            float b0a = g_b0[d * HH + col];
            float b0b = g_b0[d * HH + col + 1];
#pragma unroll
            for (int rr = 0; rr < 2; rr++) {
                int rowin = wm * 32 + mt * 16 + er + rr * 8;
                int t = tb + rowin;
                float* dst = g_X0 + ((size_t)(d * TT + t) * BB + b) * HH + col;
                *(float2*)dst = make_float2(acc[mt][nt][rr * 2 + 0] + b0a,
                                            acc[mt][nt][rr * 2 + 1] + b0b);
            }
        }
    }
}

// ---------- gather + concat + FC ----------
__global__ void final_kernel(const int* __restrict__ pad,
                             const float* __restrict__ W_fc, const float* __restrict__ b_fc,
                             float* __restrict__ out) {
    __shared__ float cs[8][1024];
    const int sub  = threadIdx.x >> 6;
    const int lane = threadIdx.x & 63;
    const int r = blockIdx.x * 8 + sub;
    const int b = r >> 8;
    const int t = r & 255;
    const int p = pad[b];
    const int tt = (t < p) ? (p - t - 1) : t;
    const float* a0 = g_o2 + ((size_t)(0 * TT + t)  * BB + b) * HH;
    const float* a1 = g_o2 + ((size_t)(1 * TT + tt) * BB + b) * HH;
#pragma unroll
    for (int i = 0; i < 4; i++) {
        int j = lane * 4 + i * 256;
        float4 vv = (j < 512) ? *(const float4*)(a0 + j) : *(const float4*)(a1 + j - 512);
        *(float4*)(&cs[sub][j]) = vv;
    }
    __syncthreads();
    if (lane < NCLS) {
        float acc = b_fc[lane];
#pragma unroll 8
        for (int k = 0; k < 1024; k++) acc = fmaf(cs[sub][k], W_fc[k * NCLS + lane], acc);
        out[(size_t)r * NCLS + lane] = acc;
    }
}

// ---------- host launcher ----------
extern "C" void kernel_launch(void* const* d_in, const int* in_sizes, int n_in,
                              void* d_out, int out_size) {
    (void)in_sizes; (void)n_in; (void)out_size;
    const float* x      = (const float*)d_in[0];
    const float* rx     = (const float*)d_in[1];
    const int*   pad    = (const int*)  d_in[2];
    const float* W_emb  = (const float*)d_in[4];
    const float* b_emb  = (const float*)d_in[5];
    const float* Wx_l2r = (const float*)d_in[6];
    const float* bx_l2r = (const float*)d_in[7];
    const float* Wh_l2r = (const float*)d_in[8];
    const float* bh_l2r = (const float*)d_in[9];
    const float* Wx_r2l = (const float*)d_in[10];
    const float* bx_r2l = (const float*)d_in[11];
    const float* Wh_r2l = (const float*)d_in[12];
    const float* bh_r2l = (const float*)d_in[13];
    const float* ln_g   = (const float*)d_in[14];
    const float* ln_b   = (const float*)d_in[15];
    const float* W_fc   = (const float*)d_in[16];
    const float* b_fc   = (const float*)d_in[17];
    float* out = (float*)d_out;

    static int attr_done = 0;
    if (!attr_done) {
        cudaFuncSetAttribute(persist_kernel, cudaFuncAttributeMaxDynamicSharedMemorySize, DSMEM);
        cudaFuncSetAttribute(x0mma_kernel, cudaFuncAttributeMaxDynamicSharedMemorySize, X0_DS);
        attr_done = 1;
    }

    // launch order chosen so persist_kernel is the 4th launch (= ncu capture slot)
    prolog_a<<<8240, 256>>>(x, rx, W_emb, b_emb, Wx_l2r, bx_l2r, Wx_r2l, bx_r2l,
                            Wh_l2r, bh_l2r, Wh_r2l, bh_r2l);
    w0conv_kernel<<<dim3(16, 10, 2), dim3(32, 8)>>>();
    x0mma_kernel<<<dim3(4, 256, 2), 512, X0_DS>>>();

    persist_kernel<<<GRID_P, 512, DSMEM>>>(ln_g, ln_b);

    final_kernel<<<4096, 512>>>(pad, W_fc, b_fc, out);
}